// round 2
// baseline (speedup 1.0000x reference)
#include <cuda_runtime.h>
#include <math.h>

typedef unsigned long long u64;

// fp32x2 packed math (SASS FFMA2) — ptxas only emits via explicit PTX.
__device__ __forceinline__ u64 ffma2(u64 a, u64 b, u64 c) {
    u64 d; asm("fma.rn.f32x2 %0, %1, %2, %3;" : "=l"(d) : "l"(a), "l"(b), "l"(c));
    return d;
}
__device__ __forceinline__ u64 pack2(float x, float y) {
    u64 d; asm("mov.b64 %0, {%1, %2};" : "=l"(d) : "f"(x), "f"(y));
    return d;
}
__device__ __forceinline__ float2 unpack2(u64 v) {
    float2 r; asm("mov.b64 {%0, %1}, %2;" : "=f"(r.x), "=f"(r.y) : "l"(v));
    return r;
}

// Problem constants
constexpr int T    = 64;
constexpr int B    = 2048;
constexpr int H    = 256;
constexpr int H1   = 64;
constexpr int H2   = 64;
constexpr int OUTD = 601;

// GRU tiling
constexpr int TB  = 32;        // batches per block
constexpr int TJ  = 64;        // hidden columns per block
constexpr int KK  = 64;        // k chunk
constexpr int WCP = KK + 4;    // padded w chunk stride (68) -> conflict-free LDS.128
constexpr int HTP = 36;        // padded stride for transposed h tile [k][batch]
// smem floats: hs_t 256*36 = 9216 ; wc 3*64*68 = 13056
constexpr int GRU_SMEM = (256 * HTP + 3 * TJ * WCP) * 4;   // 89088 B -> 2 blocks/SM

// MLP tiling
constexpr int RROWS = 64;  // rows per block
// smem floats:
//   xt  @ 0      : 64*256 = 16384   (aliased by w3s tile 64*128 = 8192 in stage 3)
//   w1s @ 16384  : 64*260 = 16640   (aliased by w2s 64*68 = 4352 in stage 2)
//   h1s @ 33024  : 64*64  = 4096
//   h2t @ 37120  : 64*66  = 4224    (transposed [k][row])
constexpr int MLP_SMEM = (16384 + 16640 + 4096 + 4224) * 4;  // 165376 B

// Scratch: GRU hidden states for all timesteps (feeds the MLP).
__device__ float g_ys[(size_t)T * B * H];   // 128 MB

// ---------------------------------------------------------------------------
// GRU step with packed fp32x2 math. h tile kept transposed+swizzled in smem.
// ---------------------------------------------------------------------------
__global__ void __launch_bounds__(256, 2)
gru_step_kernel(int t,
                const float* __restrict__ h0,
                const float* __restrict__ x,
                const float* __restrict__ w_hh,
                const float* __restrict__ w_ih,
                const float* __restrict__ b_ih,
                const float* __restrict__ b_hh)
{
    extern __shared__ float sm[];
    float* hs_t = sm;                 // [256][HTP]  h^T: [k][batch], swizzled
    float* wc   = sm + 256 * HTP;     // [3][TJ][WCP]

    const float* hprev = (t == 0) ? h0 : (g_ys + (size_t)(t - 1) * B * H);
    float* hout = g_ys + (size_t)t * B * H;

    const int j0  = blockIdx.x * TJ;
    const int b0  = blockIdx.y * TB;
    const int tid = threadIdx.x;

    // Load h tile transposed: global reads coalesced (k = lane-consecutive),
    // smem column swizzled by ((k&24)>>1) to kill the stride-36 STS conflicts.
    for (int f = tid; f < TB * 256; f += 256) {
        int b = f >> 8;          // constant within each iteration
        int k = f & 255;         // lane-consecutive
        int c = b ^ ((k & 24) >> 1);
        hs_t[k * HTP + c] = hprev[(size_t)(b0 + b) * H + k];
    }

    const int j  = tid & (TJ - 1);   // hidden col within tile
    const int bg = tid >> 6;         // batch group (8 batches = 4 pairs)

    u64 accr[4], accz[4], accn[4];
    #pragma unroll
    for (int i = 0; i < 4; i++) { accr[i] = 0ull; accz[i] = 0ull; accn[i] = 0ull; }

    for (int k0 = 0; k0 < H; k0 += KK) {
        __syncthreads();   // protects hs_t load (1st iter) and wc reuse
        // Stage w_hh chunk: coalesced LDG, conflict-free STS
        for (int f = tid; f < 3 * TJ * KK; f += 256) {
            int kk = f & 63;
            int jj = (f >> 6) & 63;
            int g  = f >> 12;
            wc[(g * TJ + jj) * WCP + kk] =
                w_hh[((size_t)(g * H + j0 + jj)) * H + k0 + kk];
        }
        __syncthreads();

        #pragma unroll 4
        for (int kk = 0; kk < KK; kk += 4) {
            float4 wr4 = *(const float4*)&wc[(0 * TJ + j) * WCP + kk];
            float4 wz4 = *(const float4*)&wc[(1 * TJ + j) * WCP + kk];
            float4 wn4 = *(const float4*)&wc[(2 * TJ + j) * WCP + kk];
            u64 wr[4], wz[4], wn[4];
            wr[0] = pack2(wr4.x, wr4.x); wr[1] = pack2(wr4.y, wr4.y);
            wr[2] = pack2(wr4.z, wr4.z); wr[3] = pack2(wr4.w, wr4.w);
            wz[0] = pack2(wz4.x, wz4.x); wz[1] = pack2(wz4.y, wz4.y);
            wz[2] = pack2(wz4.z, wz4.z); wz[3] = pack2(wz4.w, wz4.w);
            wn[0] = pack2(wn4.x, wn4.x); wn[1] = pack2(wn4.y, wn4.y);
            wn[2] = pack2(wn4.z, wn4.z); wn[3] = pack2(wn4.w, wn4.w);

            #pragma unroll
            for (int kq = 0; kq < 4; kq++) {
                int k = k0 + kk + kq;
                int v = (k & 24) >> 1;
                const float* hp = &hs_t[k * HTP];
                // batch pairs (broadcast LDS.64, conflict-free)
                u64 h0p = *(const u64*)&hp[(bg * 8 + 0) ^ v];
                u64 h1p = *(const u64*)&hp[(bg * 8 + 2) ^ v];
                u64 h2p = *(const u64*)&hp[(bg * 8 + 4) ^ v];
                u64 h3p = *(const u64*)&hp[(bg * 8 + 6) ^ v];
                accr[0] = ffma2(h0p, wr[kq], accr[0]);
                accr[1] = ffma2(h1p, wr[kq], accr[1]);
                accr[2] = ffma2(h2p, wr[kq], accr[2]);
                accr[3] = ffma2(h3p, wr[kq], accr[3]);
                accz[0] = ffma2(h0p, wz[kq], accz[0]);
                accz[1] = ffma2(h1p, wz[kq], accz[1]);
                accz[2] = ffma2(h2p, wz[kq], accz[2]);
                accz[3] = ffma2(h3p, wz[kq], accz[3]);
                accn[0] = ffma2(h0p, wn[kq], accn[0]);
                accn[1] = ffma2(h1p, wn[kq], accn[1]);
                accn[2] = ffma2(h2p, wn[kq], accn[2]);
                accn[3] = ffma2(h3p, wn[kq], accn[3]);
            }
        }
    }

    // Epilogue: gates + state update
    const int jg = j0 + j;
    const float xw_r = w_ih[jg];
    const float xw_z = w_ih[H + jg];
    const float xw_n = w_ih[2 * H + jg];
    const float bb_r = b_ih[jg]       + b_hh[jg];
    const float bb_z = b_ih[H + jg]   + b_hh[H + jg];
    const float bi_n = b_ih[2 * H + jg];
    const float bh_n = b_hh[2 * H + jg];
    const int vv = (jg & 24) >> 1;

    #pragma unroll
    for (int p = 0; p < 4; p++) {
        float2 ar = unpack2(accr[p]);
        float2 az = unpack2(accz[p]);
        float2 an = unpack2(accn[p]);
        #pragma unroll
        for (int e = 0; e < 2; e++) {
            int bl = bg * 8 + 2 * p + e;
            float sr = e ? ar.y : ar.x;
            float sz = e ? az.y : az.x;
            float sn = e ? an.y : an.x;
            float xv = x[(size_t)t * B + b0 + bl];
            float r = 1.f / (1.f + expf(-(xv * xw_r + bb_r + sr)));
            float z = 1.f / (1.f + expf(-(xv * xw_z + bb_z + sz)));
            float n = tanhf(xv * xw_n + bi_n + r * (sn + bh_n));
            float hold = hs_t[jg * HTP + (bl ^ vv)];
            hout[(size_t)(b0 + bl) * H + jg] = (1.f - z) * n + z * hold;
        }
    }
}

// ---------------------------------------------------------------------------
// Fused MLP: y = elu(elu(ys@w1+b1)@w2+b2)@w3 + b3.
// Stage 3 uses packed fp32x2 over row pairs (h2 kept transposed in smem).
// ---------------------------------------------------------------------------
__global__ void __launch_bounds__(256)
mlp_kernel(const float* __restrict__ w1, const float* __restrict__ b1,
           const float* __restrict__ w2, const float* __restrict__ b2,
           const float* __restrict__ w3, const float* __restrict__ b3,
           float* __restrict__ out)
{
    extern __shared__ float sm[];
    float* xt  = sm;            // [RROWS][H]
    float* w1s = sm + 16384;    // [64][260] transposed w1
    float* h1s = sm + 33024;    // [RROWS][64]
    float* h2t = sm + 37120;    // [64][66]  h2 transposed: [k][row]
    float* w3s = sm;            // alias xt: [64][128]
    float* w2s = sm + 16384;    // alias w1s: [64][68]

    const int tid = threadIdx.x;
    const size_t row0 = (size_t)blockIdx.x * RROWS;

    // Load input rows + w1 (transposed, padded)
    {
        const float4* src = (const float4*)(g_ys + row0 * H);
        float4* dst = (float4*)xt;
        for (int i = tid; i < RROWS * H / 4; i += 256) dst[i] = src[i];
    }
    for (int f = tid; f < H * H1; f += 256) {
        int jj = f & 63; int k = f >> 6;
        w1s[jj * 260 + k] = w1[f];
    }
    __syncthreads();

    const int jp = tid & 31;    // column pair: j = 2jp, 2jp+1
    const int rg = tid >> 5;    // row group: rows rg*8 .. rg*8+7

    // ---- Stage 1: h1 = elu(xt @ w1 + b1) ----
    {
        float acc[8][2];
        #pragma unroll
        for (int i = 0; i < 8; i++) { acc[i][0] = 0.f; acc[i][1] = 0.f; }
        #pragma unroll 4
        for (int k = 0; k < H; k += 4) {
            float4 wa = *(const float4*)&w1s[(2 * jp) * 260 + k];
            float4 wb = *(const float4*)&w1s[(2 * jp + 1) * 260 + k];
            #pragma unroll
            for (int i = 0; i < 8; i++) {
                float4 xv = *(const float4*)&xt[(rg * 8 + i) * H + k];
                acc[i][0] += xv.x * wa.x + xv.y * wa.y + xv.z * wa.z + xv.w * wa.w;
                acc[i][1] += xv.x * wb.x + xv.y * wb.y + xv.z * wb.z + xv.w * wb.w;
            }
        }
        float ba = b1[2 * jp], bb = b1[2 * jp + 1];
        #pragma unroll
        for (int i = 0; i < 8; i++) {
            float va = acc[i][0] + ba; va = va > 0.f ? va : expm1f(va);
            float vb = acc[i][1] + bb; vb = vb > 0.f ? vb : expm1f(vb);
            h1s[(rg * 8 + i) * 64 + 2 * jp]     = va;
            h1s[(rg * 8 + i) * 64 + 2 * jp + 1] = vb;
        }
    }
    __syncthreads();   // stage1 readers of xt/w1s done before aliasing writes

    // Load w2 (transposed, padded) into w1s region
    for (int f = tid; f < H1 * H2; f += 256) {
        int jj = f & 63; int k = f >> 6;
        w2s[jj * 68 + k] = w2[f];
    }
    __syncthreads();

    // ---- Stage 2: h2 = elu(h1 @ w2 + b2), written TRANSPOSED to h2t ----
    {
        float acc[8][2];
        #pragma unroll
        for (int i = 0; i < 8; i++) { acc[i][0] = 0.f; acc[i][1] = 0.f; }
        #pragma unroll
        for (int k = 0; k < H1; k += 4) {
            float4 wa = *(const float4*)&w2s[(2 * jp) * 68 + k];
            float4 wb = *(const float4*)&w2s[(2 * jp + 1) * 68 + k];
            #pragma unroll
            for (int i = 0; i < 8; i++) {
                float4 xv = *(const float4*)&h1s[(rg * 8 + i) * 64 + k];
                acc[i][0] += xv.x * wa.x + xv.y * wa.y + xv.z * wa.z + xv.w * wa.w;
                acc[i][1] += xv.x * wb.x + xv.y * wb.y + xv.z * wb.z + xv.w * wb.w;
            }
        }
        float ba = b2[2 * jp], bb = b2[2 * jp + 1];
        #pragma unroll
        for (int i = 0; i < 8; i++) {
            int row = rg * 8 + i;
            float va = acc[i][0] + ba; va = va > 0.f ? va : expm1f(va);
            float vb = acc[i][1] + bb; vb = vb > 0.f ? vb : expm1f(vb);
            h2t[(2 * jp) * 66 + row]     = va;
            h2t[(2 * jp + 1) * 66 + row] = vb;
        }
    }
    __syncthreads();

    // ---- Stage 3: y = h2 @ w3 + b3, packed fp32x2 over row pairs ----
    const int cp  = tid & 31;   // strided cols: c0 + cp + 32q
    const int rg3 = tid >> 5;

    for (int c0 = 0; c0 < OUTD; c0 += 128) {
        // load w3 tile [64][128] into w3s (aliases xt; prior sync protects)
        for (int f = tid; f < 64 * 128; f += 256) {
            int c = f & 127; int k = f >> 7;
            int cg = c0 + c;
            w3s[k * 128 + c] = (cg < OUTD) ? w3[(size_t)k * OUTD + cg] : 0.f;
        }
        __syncthreads();

        u64 acc[4][4];
        #pragma unroll
        for (int rp = 0; rp < 4; rp++)
            #pragma unroll
            for (int q = 0; q < 4; q++) acc[rp][q] = 0ull;

        #pragma unroll 4
        for (int k = 0; k < H2; k++) {
            u64 wd[4];
            #pragma unroll
            for (int q = 0; q < 4; q++) {
                float w = w3s[k * 128 + cp + 32 * q];
                wd[q] = pack2(w, w);
            }
            const float* hp = &h2t[k * 66 + rg3 * 8];
            u64 hv0 = *(const u64*)(hp + 0);
            u64 hv1 = *(const u64*)(hp + 2);
            u64 hv2 = *(const u64*)(hp + 4);
            u64 hv3 = *(const u64*)(hp + 6);
            #pragma unroll
            for (int q = 0; q < 4; q++) {
                acc[0][q] = ffma2(hv0, wd[q], acc[0][q]);
                acc[1][q] = ffma2(hv1, wd[q], acc[1][q]);
                acc[2][q] = ffma2(hv2, wd[q], acc[2][q]);
                acc[3][q] = ffma2(hv3, wd[q], acc[3][q]);
            }
        }

        #pragma unroll
        for (int q = 0; q < 4; q++) {
            int cg = c0 + cp + 32 * q;
            if (cg < OUTD) {
                float bq = b3[cg];
                #pragma unroll
                for (int rp = 0; rp < 4; rp++) {
                    float2 v = unpack2(acc[rp][q]);
                    size_t row = row0 + rg3 * 8 + 2 * rp;
                    out[row * OUTD + cg]       = v.x + bq;   // coalesced over cp
                    out[(row + 1) * OUTD + cg] = v.y + bq;
                }
            }
        }
        __syncthreads();   // before next tile overwrites w3s
    }
}

// Copy final hidden state h_T into the tail of the output.
__global__ void copy_h_kernel(float* __restrict__ out)
{
    int i = blockIdx.x * blockDim.x + threadIdx.x;
    if (i < B * H / 4) {
        const float4* src = (const float4*)(g_ys + (size_t)(T - 1) * B * H);
        ((float4*)out)[i] = src[i];
    }
}

// ---------------------------------------------------------------------------
extern "C" void kernel_launch(void* const* d_in, const int* in_sizes, int n_in,
                              void* d_out, int out_size)
{
    const float* x    = (const float*)d_in[0];
    const float* h0   = (const float*)d_in[1];
    const float* w_ih = (const float*)d_in[2];
    const float* w_hh = (const float*)d_in[3];
    const float* b_ih = (const float*)d_in[4];
    const float* b_hh = (const float*)d_in[5];
    const float* w1   = (const float*)d_in[6];
    const float* b1   = (const float*)d_in[7];
    const float* w2   = (const float*)d_in[8];
    const float* b2   = (const float*)d_in[9];
    const float* w3   = (const float*)d_in[10];
    const float* b3   = (const float*)d_in[11];
    float* out = (float*)d_out;

    cudaFuncSetAttribute(gru_step_kernel,
                         cudaFuncAttributeMaxDynamicSharedMemorySize, GRU_SMEM);
    cudaFuncSetAttribute(mlp_kernel,
                         cudaFuncAttributeMaxDynamicSharedMemorySize, MLP_SMEM);

    dim3 ggrid(H / TJ, B / TB);   // (4, 64)
    for (int t = 0; t < T; ++t) {
        gru_step_kernel<<<ggrid, 256, GRU_SMEM>>>(t, h0, x, w_hh, w_ih, b_ih, b_hh);
    }

    mlp_kernel<<<(T * B) / RROWS, 256, MLP_SMEM>>>(w1, b1, w2, b2, w3, b3, out);

    copy_h_kernel<<<(B * H / 4 + 255) / 256, 256>>>(out + (size_t)T * B * OUTD);
}

// round 4
// speedup vs baseline: 1.8499x; 1.8499x over previous
#include <cuda_runtime.h>
#include <cuda_bf16.h>
#include <math.h>
#include <string.h>

typedef unsigned int u32;
typedef unsigned long long u64;

// ---------------------------------------------------------------------------
// Problem constants
// ---------------------------------------------------------------------------
constexpr int T    = 64;
constexpr int B    = 2048;
constexpr int H    = 256;
constexpr int H1   = 64;
constexpr int H2   = 64;
constexpr int OUTD = 601;

// ---------------------------------------------------------------------------
// PTX helpers (HMMA / ldmatrix / cp.async / packed fp32x2) — all sm_80+
// ---------------------------------------------------------------------------
__device__ __forceinline__ u32 smem_u32(const void* p) {
    u32 a;
    asm("{ .reg .u64 t; cvta.to.shared.u64 t, %1; cvt.u32.u64 %0, t; }"
        : "=r"(a) : "l"(p));
    return a;
}
__device__ __forceinline__ void ldsm_x4(u32& r0, u32& r1, u32& r2, u32& r3, u32 addr) {
    asm volatile("ldmatrix.sync.aligned.m8n8.x4.shared.b16 {%0,%1,%2,%3}, [%4];"
                 : "=r"(r0), "=r"(r1), "=r"(r2), "=r"(r3) : "r"(addr));
}
__device__ __forceinline__ void mma_bf16(float* d, const u32* a, const u32* b) {
    asm volatile(
        "mma.sync.aligned.m16n8k16.row.col.f32.bf16.bf16.f32 "
        "{%0,%1,%2,%3}, {%4,%5,%6,%7}, {%8,%9}, {%0,%1,%2,%3};"
        : "+f"(d[0]), "+f"(d[1]), "+f"(d[2]), "+f"(d[3])
        : "r"(a[0]), "r"(a[1]), "r"(a[2]), "r"(a[3]), "r"(b[0]), "r"(b[1]));
}
__device__ __forceinline__ void cp16(u32 dst, const void* src) {
    asm volatile("cp.async.ca.shared.global [%0], [%1], 16;" :: "r"(dst), "l"(src));
}
__device__ __forceinline__ void cp_wait_all() {
    asm volatile("cp.async.wait_all;" ::: "memory");
}
#define SWZ(o) ((o) ^ (((o) >> 3) & 0x70))

__device__ __forceinline__ u32 bf2u(__nv_bfloat162 v) {
    u32 r; memcpy(&r, &v, 4); return r;
}
// fp32x2 packed math for MLP stage-3 (proved a win in R2)
__device__ __forceinline__ u64 ffma2(u64 a, u64 b, u64 c) {
    u64 d; asm("fma.rn.f32x2 %0, %1, %2, %3;" : "=l"(d) : "l"(a), "l"(b), "l"(c));
    return d;
}
__device__ __forceinline__ u64 pack2(float x, float y) {
    u64 d; asm("mov.b64 %0, {%1, %2};" : "=l"(d) : "f"(x), "f"(y));
    return d;
}
__device__ __forceinline__ float2 unpack2(u64 v) {
    float2 r; asm("mov.b64 {%0, %1}, %2;" : "=f"(r.x), "=f"(r.y) : "l"(v));
    return r;
}

// ---------------------------------------------------------------------------
// Device scratch
// ---------------------------------------------------------------------------
__device__ float g_ys[(size_t)T * B * H];                 // all hidden states
__device__ __nv_bfloat16 g_whi[(size_t)3 * H * H];        // w_hh split hi
__device__ __nv_bfloat16 g_wlo[(size_t)3 * H * H];        // w_hh split lo

__global__ void prep_w_kernel(const float* __restrict__ w_hh)
{
    int i = blockIdx.x * blockDim.x + threadIdx.x;
    if (i < 3 * H * H) {
        float w = w_hh[i];
        __nv_bfloat16 hi = __float2bfloat16(w);
        g_whi[i] = hi;
        g_wlo[i] = __float2bfloat16(w - __bfloat162float(hi));
    }
}

// ---------------------------------------------------------------------------
// GRU step via HMMA (mma.sync m16n8k16 bf16, split hi/lo 3-term).
// Block: 64 batches (M) x 64 hidden j -> 192 gate cols (N). Grid (4, 32).
// 8 warps: 2 (M) x 4 (N); warp tile 32x48. K chunked by 64.
// ---------------------------------------------------------------------------
constexpr int GMB = 64;   // batches per block
constexpr int GJ  = 64;   // hidden cols per block
constexpr int GK  = 64;   // K chunk

// smem byte offsets
constexpr int SM_PAR  = 0;          // 7*64 f32 = 1792
constexpr int SM_HOLD = 1792;       // hold[64][66] f32 = 16896 -> ends 18688
constexpr int SM_AB   = 18688;      // 128-aligned
constexpr int SM_AHI  = SM_AB;              // [64][128B]  = 8192
constexpr int SM_ALO  = SM_AB + 8192;
constexpr int SM_WHI  = SM_AB + 16384;      // [192][128B] = 24576
constexpr int SM_WLO  = SM_AB + 40960;
constexpr int GRU_SMEM = SM_AB + 65536;     // 84224 B
// accum reuse: [64][196] f32 = 50176 <= 65536 in the A/W region

__global__ void __launch_bounds__(256)
gru_tc_kernel(int t,
              const float* __restrict__ h0,
              const float* __restrict__ x,
              const float* __restrict__ w_ih,
              const float* __restrict__ b_ih,
              const float* __restrict__ b_hh)
{
    extern __shared__ char smem[];
    float* sparam = (float*)(smem + SM_PAR);
    float* hold   = (float*)(smem + SM_HOLD);
    float* accs   = (float*)(smem + SM_AB);
    const u32 sb = smem_u32(smem);

    const int tid  = threadIdx.x;
    const int wid  = tid >> 5;
    const int lane = tid & 31;
    const int j0 = blockIdx.x * GJ;
    const int b0 = blockIdx.y * GMB;
    const int jx = blockIdx.x;   // K-chunk index containing cols j0..j0+63

    const float* hprev = (t == 0) ? h0 : (g_ys + (size_t)(t - 1) * B * H);
    float* hout = g_ys + (size_t)t * B * H;

    if (tid < GJ) {
        int jg = j0 + tid;
        sparam[0 * 64 + tid] = w_ih[jg];
        sparam[1 * 64 + tid] = w_ih[H + jg];
        sparam[2 * 64 + tid] = w_ih[2 * H + jg];
        sparam[3 * 64 + tid] = b_ih[jg]         + b_hh[jg];
        sparam[4 * 64 + tid] = b_ih[H + jg]     + b_hh[H + jg];
        sparam[5 * 64 + tid] = b_ih[2 * H + jg];
        sparam[6 * 64 + tid] = b_hh[2 * H + jg];
    }

    const int wm = wid >> 2;   // 0..1  (M)
    const int wn = wid & 3;    // 0..3  (N)

    float acc[2][6][4];
    #pragma unroll
    for (int mt = 0; mt < 2; mt++)
        #pragma unroll
        for (int nt = 0; nt < 6; nt++)
            #pragma unroll
            for (int q = 0; q < 4; q++) acc[mt][nt][q] = 0.f;

    // ldmatrix lane address components
    const int a_row  = lane & 15;             // row within 16
    const int a_colh = (lane >> 4) * 16;      // 16B half (k0 / k8)
    const int b_row  = ((lane >> 4) << 3) + (lane & 7);   // n within 16
    const int b_colh = ((lane >> 3) & 1) * 16;            // k half

    for (int c = 0; c < 4; c++) {
        if (c) __syncthreads();   // prior MMA reads done before restaging

        // --- stage A: h chunk fp32 -> bf16 hi/lo, SW128 [64 rows][64 k] ---
        #pragma unroll
        for (int f = tid; f < GMB * 32; f += 256) {
            int row = f >> 5, kp = f & 31;
            float2 hv = *(const float2*)&hprev[(size_t)(b0 + row) * H + c * GK + 2 * kp];
            __nv_bfloat162 h2 = __floats2bfloat162_rn(hv.x, hv.y);
            float rx = hv.x - __bfloat162float(h2.x);
            float ry = hv.y - __bfloat162float(h2.y);
            __nv_bfloat162 l2 = __floats2bfloat162_rn(rx, ry);
            u32 off = SWZ((u32)(row * 128 + kp * 4));
            *(u32*)(smem + SM_AHI + off) = bf2u(h2);
            *(u32*)(smem + SM_ALO + off) = bf2u(l2);
            if (c == jx) *(float2*)&hold[row * 66 + 2 * kp] = hv;   // fp32 h_old
        }
        // --- stage W: pre-split bf16, cp.async 16B, SW128 [192 rows][64 k] ---
        #pragma unroll
        for (int f = tid; f < 192 * 8; f += 256) {
            int row = f >> 3, cc = f & 7;
            int g = row >> 6, jj = row & 63;
            size_t src = ((size_t)(g * H + j0 + jj)) * H + c * GK + cc * 8;
            u32 dsto = (u32)(row * 128) + (u32)((cc * 16) ^ ((row & 7) << 4));
            cp16(sb + SM_WHI + dsto, g_whi + src);
            cp16(sb + SM_WLO + dsto, g_wlo + src);
        }
        cp_wait_all();
        __syncthreads();

        // --- MMA: 4 k-steps x (2 m-tiles x 6 n-tiles) x 3 split terms ---
        #pragma unroll
        for (int ks = 0; ks < 4; ks++) {
            u32 ahi[2][4], alo[2][4], bhi[6][2], blo[6][2];
            #pragma unroll
            for (int mt = 0; mt < 2; mt++) {
                int r = wm * 32 + mt * 16 + a_row;
                u32 off = (u32)(r * 128) + (u32)((ks * 32 + a_colh) ^ ((r & 7) << 4));
                ldsm_x4(ahi[mt][0], ahi[mt][1], ahi[mt][2], ahi[mt][3], sb + SM_AHI + off);
                ldsm_x4(alo[mt][0], alo[mt][1], alo[mt][2], alo[mt][3], sb + SM_ALO + off);
            }
            #pragma unroll
            for (int p = 0; p < 3; p++) {
                int r = wn * 48 + p * 16 + b_row;
                u32 off = (u32)(r * 128) + (u32)((ks * 32 + b_colh) ^ ((r & 7) << 4));
                ldsm_x4(bhi[2 * p][0], bhi[2 * p][1], bhi[2 * p + 1][0], bhi[2 * p + 1][1],
                        sb + SM_WHI + off);
                ldsm_x4(blo[2 * p][0], blo[2 * p][1], blo[2 * p + 1][0], blo[2 * p + 1][1],
                        sb + SM_WLO + off);
            }
            #pragma unroll
            for (int mt = 0; mt < 2; mt++)
                #pragma unroll
                for (int nt = 0; nt < 6; nt++) {
                    mma_bf16(acc[mt][nt], ahi[mt], bhi[nt]);   // hi*whi
                    mma_bf16(acc[mt][nt], ahi[mt], blo[nt]);   // hi*wlo
                    mma_bf16(acc[mt][nt], alo[mt], bhi[nt]);   // lo*whi
                }
        }
    }
    __syncthreads();

    // --- dump accumulators to smem [64 m][196] (reuses A/W region) ---
    #pragma unroll
    for (int mt = 0; mt < 2; mt++) {
        int r = wm * 32 + mt * 16 + (lane >> 2);
        #pragma unroll
        for (int nt = 0; nt < 6; nt++) {
            int cl = wn * 48 + nt * 8 + 2 * (lane & 3);
            *(float2*)&accs[r * 196 + cl]       = make_float2(acc[mt][nt][0], acc[mt][nt][1]);
            *(float2*)&accs[(r + 8) * 196 + cl] = make_float2(acc[mt][nt][2], acc[mt][nt][3]);
        }
    }
    __syncthreads();

    // --- gate math + blend + coalesced store ---
    #pragma unroll
    for (int f = tid; f < GMB * GJ; f += 256) {
        int b = f >> 6, j = f & 63;
        float rr = accs[b * 196 + j];
        float zz = accs[b * 196 + 64 + j];
        float nn = accs[b * 196 + 128 + j];
        float xv = x[(size_t)t * B + b0 + b];
        float r = 1.f / (1.f + expf(-(xv * sparam[j]      + sparam[192 + j] + rr)));
        float z = 1.f / (1.f + expf(-(xv * sparam[64 + j] + sparam[256 + j] + zz)));
        float n = tanhf(xv * sparam[128 + j] + sparam[320 + j] + r * (nn + sparam[384 + j]));
        float ho = hold[b * 66 + j];
        hout[(size_t)(b0 + b) * H + j0 + j] = (1.f - z) * n + z * ho;
    }
}

// ---------------------------------------------------------------------------
// Fused MLP (R2 version, measured ~190us): fp32, fp32x2 in stage 3.
// ---------------------------------------------------------------------------
constexpr int RROWS = 64;
constexpr int MLP_SMEM = (16384 + 16640 + 4096 + 4224) * 4;  // 165376 B

__global__ void __launch_bounds__(256)
mlp_kernel(const float* __restrict__ w1, const float* __restrict__ b1,
           const float* __restrict__ w2, const float* __restrict__ b2,
           const float* __restrict__ w3, const float* __restrict__ b3,
           float* __restrict__ out)
{
    extern __shared__ float sm[];
    float* xt  = sm;            // [RROWS][H]
    float* w1s = sm + 16384;    // [64][260]
    float* h1s = sm + 33024;    // [RROWS][64]
    float* h2t = sm + 37120;    // [64][66]  transposed [k][row]
    float* w3s = sm;            // alias xt
    float* w2s = sm + 16384;    // alias w1s

    const int tid = threadIdx.x;
    const size_t row0 = (size_t)blockIdx.x * RROWS;

    {
        const float4* src = (const float4*)(g_ys + row0 * H);
        float4* dst = (float4*)xt;
        for (int i = tid; i < RROWS * H / 4; i += 256) dst[i] = src[i];
    }
    for (int f = tid; f < H * H1; f += 256) {
        int jj = f & 63; int k = f >> 6;
        w1s[jj * 260 + k] = w1[f];
    }
    __syncthreads();

    const int jp = tid & 31;
    const int rg = tid >> 5;

    // Stage 1
    {
        float acc[8][2];
        #pragma unroll
        for (int i = 0; i < 8; i++) { acc[i][0] = 0.f; acc[i][1] = 0.f; }
        #pragma unroll 4
        for (int k = 0; k < H; k += 4) {
            float4 wa = *(const float4*)&w1s[(2 * jp) * 260 + k];
            float4 wb = *(const float4*)&w1s[(2 * jp + 1) * 260 + k];
            #pragma unroll
            for (int i = 0; i < 8; i++) {
                float4 xv = *(const float4*)&xt[(rg * 8 + i) * H + k];
                acc[i][0] += xv.x * wa.x + xv.y * wa.y + xv.z * wa.z + xv.w * wa.w;
                acc[i][1] += xv.x * wb.x + xv.y * wb.y + xv.z * wb.z + xv.w * wb.w;
            }
        }
        float ba = b1[2 * jp], bb = b1[2 * jp + 1];
        #pragma unroll
        for (int i = 0; i < 8; i++) {
            float va = acc[i][0] + ba; va = va > 0.f ? va : expm1f(va);
            float vb = acc[i][1] + bb; vb = vb > 0.f ? vb : expm1f(vb);
            h1s[(rg * 8 + i) * 64 + 2 * jp]     = va;
            h1s[(rg * 8 + i) * 64 + 2 * jp + 1] = vb;
        }
    }
    __syncthreads();

    for (int f = tid; f < H1 * H2; f += 256) {
        int jj = f & 63; int k = f >> 6;
        w2s[jj * 68 + k] = w2[f];
    }
    __syncthreads();

    // Stage 2 (write h2 transposed)
    {
        float acc[8][2];
        #pragma unroll
        for (int i = 0; i < 8; i++) { acc[i][0] = 0.f; acc[i][1] = 0.f; }
        #pragma unroll
        for (int k = 0; k < H1; k += 4) {
            float4 wa = *(const float4*)&w2s[(2 * jp) * 68 + k];
            float4 wb = *(const float4*)&w2s[(2 * jp + 1) * 68 + k];
            #pragma unroll
            for (int i = 0; i < 8; i++) {
                float4 xv = *(const float4*)&h1s[(rg * 8 + i) * 64 + k];
                acc[i][0] += xv.x * wa.x + xv.y * wa.y + xv.z * wa.z + xv.w * wa.w;
                acc[i][1] += xv.x * wb.x + xv.y * wb.y + xv.z * wb.z + xv.w * wb.w;
            }
        }
        float ba = b2[2 * jp], bb = b2[2 * jp + 1];
        #pragma unroll
        for (int i = 0; i < 8; i++) {
            int row = rg * 8 + i;
            float va = acc[i][0] + ba; va = va > 0.f ? va : expm1f(va);
            float vb = acc[i][1] + bb; vb = vb > 0.f ? vb : expm1f(vb);
            h2t[(2 * jp) * 66 + row]     = va;
            h2t[(2 * jp + 1) * 66 + row] = vb;
        }
    }
    __syncthreads();

    // Stage 3: packed fp32x2 over row pairs
    const int cp  = tid & 31;
    const int rg3 = tid >> 5;

    for (int c0 = 0; c0 < OUTD; c0 += 128) {
        for (int f = tid; f < 64 * 128; f += 256) {
            int c = f & 127; int k = f >> 7;
            int cg = c0 + c;
            w3s[k * 128 + c] = (cg < OUTD) ? w3[(size_t)k * OUTD + cg] : 0.f;
        }
        __syncthreads();

        u64 acc[4][4];
        #pragma unroll
        for (int rp = 0; rp < 4; rp++)
            #pragma unroll
            for (int q = 0; q < 4; q++) acc[rp][q] = 0ull;

        #pragma unroll 4
        for (int k = 0; k < H2; k++) {
            u64 wd[4];
            #pragma unroll
            for (int q = 0; q < 4; q++) {
                float w = w3s[k * 128 + cp + 32 * q];
                wd[q] = pack2(w, w);
            }
            const float* hp = &h2t[k * 66 + rg3 * 8];
            u64 hv0 = *(const u64*)(hp + 0);
            u64 hv1 = *(const u64*)(hp + 2);
            u64 hv2 = *(const u64*)(hp + 4);
            u64 hv3 = *(const u64*)(hp + 6);
            #pragma unroll
            for (int q = 0; q < 4; q++) {
                acc[0][q] = ffma2(hv0, wd[q], acc[0][q]);
                acc[1][q] = ffma2(hv1, wd[q], acc[1][q]);
                acc[2][q] = ffma2(hv2, wd[q], acc[2][q]);
                acc[3][q] = ffma2(hv3, wd[q], acc[3][q]);
            }
        }

        #pragma unroll
        for (int q = 0; q < 4; q++) {
            int cg = c0 + cp + 32 * q;
            if (cg < OUTD) {
                float bq = b3[cg];
                #pragma unroll
                for (int rp = 0; rp < 4; rp++) {
                    float2 v = unpack2(acc[rp][q]);
                    size_t row = row0 + rg3 * 8 + 2 * rp;
                    out[row * OUTD + cg]       = v.x + bq;
                    out[(row + 1) * OUTD + cg] = v.y + bq;
                }
            }
        }
        __syncthreads();
    }
}

__global__ void copy_h_kernel(float* __restrict__ out)
{
    int i = blockIdx.x * blockDim.x + threadIdx.x;
    if (i < B * H / 4) {
        const float4* src = (const float4*)(g_ys + (size_t)(T - 1) * B * H);
        ((float4*)out)[i] = src[i];
    }
}

// ---------------------------------------------------------------------------
extern "C" void kernel_launch(void* const* d_in, const int* in_sizes, int n_in,
                              void* d_out, int out_size)
{
    const float* x    = (const float*)d_in[0];
    const float* h0   = (const float*)d_in[1];
    const float* w_ih = (const float*)d_in[2];
    const float* w_hh = (const float*)d_in[3];
    const float* b_ih = (const float*)d_in[4];
    const float* b_hh = (const float*)d_in[5];
    const float* w1   = (const float*)d_in[6];
    const float* b1   = (const float*)d_in[7];
    const float* w2   = (const float*)d_in[8];
    const float* b2   = (const float*)d_in[9];
    const float* w3   = (const float*)d_in[10];
    const float* b3   = (const float*)d_in[11];
    float* out = (float*)d_out;

    cudaFuncSetAttribute(gru_tc_kernel,
                         cudaFuncAttributeMaxDynamicSharedMemorySize, GRU_SMEM);
    cudaFuncSetAttribute(mlp_kernel,
                         cudaFuncAttributeMaxDynamicSharedMemorySize, MLP_SMEM);

    prep_w_kernel<<<(3 * H * H + 255) / 256, 256>>>(w_hh);

    dim3 ggrid(H / GJ, B / GMB);   // (4, 32) = 128 blocks
    for (int t = 0; t < T; ++t) {
        gru_tc_kernel<<<ggrid, 256, GRU_SMEM>>>(t, h0, x, w_ih, b_ih, b_hh);
    }

    mlp_kernel<<<(T * B) / RROWS, 256, MLP_SMEM>>>(w1, b1, w2, b2, w3, b3, out);

    copy_h_kernel<<<(B * H / 4 + 255) / 256, 256>>>(out + (size_t)T * B * OUTD);
}

// round 5
// speedup vs baseline: 2.0703x; 1.1191x over previous
#include <cuda_runtime.h>
#include <cuda_bf16.h>
#include <math.h>
#include <string.h>

typedef unsigned int u32;
typedef unsigned long long u64;

// ---------------------------------------------------------------------------
// Problem constants
// ---------------------------------------------------------------------------
constexpr int T    = 64;
constexpr int B    = 2048;
constexpr int H    = 256;
constexpr int H1   = 64;
constexpr int H2   = 64;
constexpr int OUTD = 601;

// ---------------------------------------------------------------------------
// PTX helpers (HMMA / ldmatrix / cp.async / packed fp32x2) — all sm_80+
// ---------------------------------------------------------------------------
__device__ __forceinline__ u32 smem_u32(const void* p) {
    u32 a;
    asm("{ .reg .u64 t; cvta.to.shared.u64 t, %1; cvt.u32.u64 %0, t; }"
        : "=r"(a) : "l"(p));
    return a;
}
__device__ __forceinline__ void ldsm_x4(u32& r0, u32& r1, u32& r2, u32& r3, u32 addr) {
    asm volatile("ldmatrix.sync.aligned.m8n8.x4.shared.b16 {%0,%1,%2,%3}, [%4];"
                 : "=r"(r0), "=r"(r1), "=r"(r2), "=r"(r3) : "r"(addr));
}
__device__ __forceinline__ void mma_bf16(float* d, const u32* a, const u32* b) {
    asm volatile(
        "mma.sync.aligned.m16n8k16.row.col.f32.bf16.bf16.f32 "
        "{%0,%1,%2,%3}, {%4,%5,%6,%7}, {%8,%9}, {%0,%1,%2,%3};"
        : "+f"(d[0]), "+f"(d[1]), "+f"(d[2]), "+f"(d[3])
        : "r"(a[0]), "r"(a[1]), "r"(a[2]), "r"(a[3]), "r"(b[0]), "r"(b[1]));
}
__device__ __forceinline__ void cp16(u32 dst, const void* src) {
    asm volatile("cp.async.ca.shared.global [%0], [%1], 16;" :: "r"(dst), "l"(src));
}
__device__ __forceinline__ void cp_wait_all() {
    asm volatile("cp.async.wait_all;" ::: "memory");
}
__device__ __forceinline__ u32 bf2u(__nv_bfloat162 v) {
    u32 r; memcpy(&r, &v, 4); return r;
}
// fp32x2 packed math for MLP stage-3
__device__ __forceinline__ u64 ffma2(u64 a, u64 b, u64 c) {
    u64 d; asm("fma.rn.f32x2 %0, %1, %2, %3;" : "=l"(d) : "l"(a), "l"(b), "l"(c));
    return d;
}
__device__ __forceinline__ u64 pack2(float x, float y) {
    u64 d; asm("mov.b64 %0, {%1, %2};" : "=l"(d) : "f"(x), "f"(y));
    return d;
}
__device__ __forceinline__ float2 unpack2(u64 v) {
    float2 r; asm("mov.b64 {%0, %1}, %2;" : "=f"(r.x), "=f"(r.y) : "l"(v));
    return r;
}

// ---------------------------------------------------------------------------
// Device scratch
// ---------------------------------------------------------------------------
__device__ float g_ys[(size_t)T * B * H];                 // all hidden states
__device__ __nv_bfloat16 g_whi[(size_t)3 * H * H];        // w_hh split hi
__device__ __nv_bfloat16 g_wlo[(size_t)3 * H * H];        // w_hh split lo

// grid barrier state (padded to separate cache lines)
__device__ u32 g_bar_cnt = 0;
__device__ u32 g_bar_pad[63];
__device__ u32 g_bar_gen = 0;

__global__ void prep_w_kernel(const float* __restrict__ w_hh)
{
    int i = blockIdx.x * blockDim.x + threadIdx.x;
    if (i < 3 * H * H) {
        float w = w_hh[i];
        __nv_bfloat16 hi = __float2bfloat16(w);
        g_whi[i] = hi;
        g_wlo[i] = __float2bfloat16(w - __bfloat162float(hi));
    }
}

// ---------------------------------------------------------------------------
// Persistent GRU: all 64 timesteps in ONE launch.
// 128 blocks = 4 j-chunks x 32 batch-groups; 1 block/SM, all co-resident.
// Weights (bf16 hi/lo, SW128) staged in smem ONCE, reused every step.
// Per-step: double-buffered A-chunk staging, register-resident epilogue,
// generation-counter grid barrier between steps.
// ---------------------------------------------------------------------------
constexpr int NBLK = 128;
// smem byte offsets
constexpr int SM_W    = 0;        // Whi: [4 chunks][192 rows][128B] = 98304
constexpr int SM_WLO_OFF = 98304; // Wlo at +98304
constexpr int SM_A    = 196608;   // 2 bufs x (hi 8192 + lo 8192) = 32768
constexpr int SM_PRM  = 229376;   // 7*64 f32 = 1792
constexpr int GRU_SMEM = 231168;  // <= 232448 opt-in limit

__global__ void __launch_bounds__(256)
gru_persist(const float* __restrict__ h0,
            const float* __restrict__ x,
            const float* __restrict__ w_ih,
            const float* __restrict__ b_ih,
            const float* __restrict__ b_hh)
{
    extern __shared__ char smem[];
    const u32 sb = smem_u32(smem);
    float* sparam = (float*)(smem + SM_PRM);

    const int tid  = threadIdx.x;
    const int wid  = tid >> 5;
    const int lane = tid & 31;
    const int jc = blockIdx.x & 3;
    const int bg = blockIdx.x >> 2;
    const int j0 = jc * 64;
    const int b0 = bg * 64;
    const int wm = wid >> 2;   // 0..1 (M)
    const int wn = wid & 3;    // 0..3 (N: j-groups of 16, all 3 gates)

    u32 gen0 = 0;
    if (tid == 0) gen0 = atomicAdd(&g_bar_gen, 0);   // relaxed read, pre-arrival

    // t-invariant gate params
    if (tid < 64) {
        int jg = j0 + tid;
        sparam[tid]        = w_ih[jg];
        sparam[64 + tid]   = w_ih[H + jg];
        sparam[128 + tid]  = w_ih[2 * H + jg];
        sparam[192 + tid]  = b_ih[jg]         + b_hh[jg];
        sparam[256 + tid]  = b_ih[H + jg]     + b_hh[H + jg];
        sparam[320 + tid]  = b_ih[2 * H + jg];
        sparam[384 + tid]  = b_hh[2 * H + jg];
    }

    // Stage ALL weights once: [chunk c][row rr = g*64+jj][128B], SW128, hi+lo
    for (int c = 0; c < 4; c++) {
        for (int f = tid; f < 192 * 8; f += 256) {
            int rr = f >> 3, cc = f & 7;
            int g = rr >> 6, jj = rr & 63;
            size_t src = ((size_t)(g * H + j0 + jj)) * H + c * 64 + cc * 8;
            u32 d = sb + SM_W + c * 24576 + rr * 128 + ((cc * 16) ^ ((rr & 7) << 4));
            cp16(d, g_whi + src);
            cp16(d + SM_WLO_OFF, g_wlo + src);
        }
    }
    cp_wait_all();
    __syncthreads();

    // ldmatrix lane address components
    const int a_row  = lane & 15;
    const int a_colh = (lane >> 4) * 16;
    const int b_row  = ((lane >> 4) << 3) + (lane & 7);
    const int b_colh = ((lane >> 3) & 1) * 16;
    const int l4 = lane >> 2;
    const int lp = lane & 3;

    for (int t = 0; t < T; t++) {
        const float* hprev = (t == 0) ? h0 : (g_ys + (size_t)(t - 1) * B * H);
        float* hout = g_ys + (size_t)t * B * H;

        // stage A chunk 0 into buf 0 (split to bf16 hi/lo, SW128)
        #pragma unroll
        for (int i = 0; i < 8; i++) {
            int f = tid + i * 256;
            int row = f >> 5, kp = f & 31;
            float2 hv = *(const float2*)&hprev[(size_t)(b0 + row) * H + 2 * kp];
            __nv_bfloat162 h2 = __floats2bfloat162_rn(hv.x, hv.y);
            __nv_bfloat162 l2 = __floats2bfloat162_rn(hv.x - __bfloat162float(h2.x),
                                                      hv.y - __bfloat162float(h2.y));
            u32 off = (u32)(row * 128) + (u32)((kp * 4) ^ ((row & 7) << 4));
            *(u32*)(smem + SM_A + off)        = bf2u(h2);
            *(u32*)(smem + SM_A + 8192 + off) = bf2u(l2);
        }
        __syncthreads();

        float acc[2][3][2][4];
        #pragma unroll
        for (int mt = 0; mt < 2; mt++)
            #pragma unroll
            for (int g = 0; g < 3; g++)
                #pragma unroll
                for (int s = 0; s < 2; s++)
                    #pragma unroll
                    for (int q = 0; q < 4; q++) acc[mt][g][s][q] = 0.f;

        for (int c = 0; c < 4; c++) {
            // prefetch next A chunk (LDG latency hides under MMA)
            float2 pre[8];
            if (c < 3) {
                #pragma unroll
                for (int i = 0; i < 8; i++) {
                    int f = tid + i * 256;
                    pre[i] = *(const float2*)
                        &hprev[(size_t)(b0 + (f >> 5)) * H + (c + 1) * 64 + 2 * (f & 31)];
                }
            }
            const u32 ab = sb + SM_A + (c & 1) * 16384;
            const u32 wb = sb + SM_W + c * 24576;

            #pragma unroll
            for (int ks = 0; ks < 4; ks++) {
                u32 ahi[2][4], alo[2][4];
                #pragma unroll
                for (int mt = 0; mt < 2; mt++) {
                    int r = wm * 32 + mt * 16 + a_row;
                    u32 off = (u32)(r * 128) + (u32)((ks * 32 + a_colh) ^ ((r & 7) << 4));
                    ldsm_x4(ahi[mt][0], ahi[mt][1], ahi[mt][2], ahi[mt][3], ab + off);
                    ldsm_x4(alo[mt][0], alo[mt][1], alo[mt][2], alo[mt][3], ab + 8192 + off);
                }
                #pragma unroll
                for (int g = 0; g < 3; g++) {
                    int rr = g * 64 + wn * 16 + b_row;
                    u32 off = (u32)(rr * 128) + (u32)((ks * 32 + b_colh) ^ ((rr & 7) << 4));
                    u32 bh[4], bl[4];
                    ldsm_x4(bh[0], bh[1], bh[2], bh[3], wb + off);
                    ldsm_x4(bl[0], bl[1], bl[2], bl[3], wb + SM_WLO_OFF + off);
                    #pragma unroll
                    for (int mt = 0; mt < 2; mt++) {
                        mma_bf16(acc[mt][g][0], ahi[mt], bh);       // hi*whi
                        mma_bf16(acc[mt][g][1], ahi[mt], bh + 2);
                        mma_bf16(acc[mt][g][0], ahi[mt], bl);       // hi*wlo
                        mma_bf16(acc[mt][g][1], ahi[mt], bl + 2);
                        mma_bf16(acc[mt][g][0], alo[mt], bh);       // lo*whi
                        mma_bf16(acc[mt][g][1], alo[mt], bh + 2);
                    }
                }
            }
            if (c < 3) {
                #pragma unroll
                for (int i = 0; i < 8; i++) {
                    int f = tid + i * 256;
                    int row = f >> 5, kp = f & 31;
                    __nv_bfloat162 h2 = __floats2bfloat162_rn(pre[i].x, pre[i].y);
                    __nv_bfloat162 l2 = __floats2bfloat162_rn(
                        pre[i].x - __bfloat162float(h2.x),
                        pre[i].y - __bfloat162float(h2.y));
                    u32 off = (u32)(row * 128) + (u32)((kp * 4) ^ ((row & 7) << 4));
                    char* base = smem + SM_A + ((c + 1) & 1) * 16384;
                    *(u32*)(base + off)        = bf2u(h2);
                    *(u32*)(base + 8192 + off) = bf2u(l2);
                }
            }
            __syncthreads();
        }

        // ---- register-resident epilogue: each lane owns r/z/n for its (b,j) ----
        #pragma unroll
        for (int mt = 0; mt < 2; mt++) {
            #pragma unroll
            for (int e = 0; e < 2; e++) {
                int rowg = b0 + wm * 32 + mt * 16 + l4 + e * 8;
                float xv = x[(size_t)t * B + rowg];
                #pragma unroll
                for (int sub = 0; sub < 2; sub++) {
                    int jl = wn * 16 + sub * 8 + 2 * lp;
                    float2 ho = *(const float2*)&hprev[(size_t)rowg * H + j0 + jl];
                    float hn0, hn1;
                    {
                        int j = jl;
                        float rr_ = acc[mt][0][sub][e * 2];
                        float zz_ = acc[mt][1][sub][e * 2];
                        float nn_ = acc[mt][2][sub][e * 2];
                        float r = 1.f / (1.f + expf(-(xv * sparam[j] + sparam[192 + j] + rr_)));
                        float z = 1.f / (1.f + expf(-(xv * sparam[64 + j] + sparam[256 + j] + zz_)));
                        float n = tanhf(xv * sparam[128 + j] + sparam[320 + j]
                                        + r * (nn_ + sparam[384 + j]));
                        hn0 = (1.f - z) * n + z * ho.x;
                    }
                    {
                        int j = jl + 1;
                        float rr_ = acc[mt][0][sub][e * 2 + 1];
                        float zz_ = acc[mt][1][sub][e * 2 + 1];
                        float nn_ = acc[mt][2][sub][e * 2 + 1];
                        float r = 1.f / (1.f + expf(-(xv * sparam[j] + sparam[192 + j] + rr_)));
                        float z = 1.f / (1.f + expf(-(xv * sparam[64 + j] + sparam[256 + j] + zz_)));
                        float n = tanhf(xv * sparam[128 + j] + sparam[320 + j]
                                        + r * (nn_ + sparam[384 + j]));
                        hn1 = (1.f - z) * n + z * ho.y;
                    }
                    *(float2*)&hout[(size_t)rowg * H + j0 + jl] = make_float2(hn0, hn1);
                }
            }
        }

        // ---- grid barrier between steps (skip after last) ----
        if (t < T - 1) {
            __threadfence();
            __syncthreads();
            if (tid == 0) {
                u32 target = gen0 + (u32)t + 1u;
                u32 old = atomicAdd(&g_bar_cnt, 1u);
                if (old == NBLK - 1) {
                    atomicExch(&g_bar_cnt, 0u);
                    __threadfence();
                    atomicExch(&g_bar_gen, target);
                } else {
                    u32 g;
                    do {
                        asm volatile("ld.acquire.gpu.global.u32 %0, [%1];"
                                     : "=r"(g) : "l"(&g_bar_gen));
                    } while ((int)(g - target) < 0);
                }
            }
            __syncthreads();
        }
    }
}

// ---------------------------------------------------------------------------
// Fused MLP (R2 version): fp32, fp32x2 in stage 3.
// ---------------------------------------------------------------------------
constexpr int RROWS = 64;
constexpr int MLP_SMEM = (16384 + 16640 + 4096 + 4224) * 4;  // 165376 B

__global__ void __launch_bounds__(256)
mlp_kernel(const float* __restrict__ w1, const float* __restrict__ b1,
           const float* __restrict__ w2, const float* __restrict__ b2,
           const float* __restrict__ w3, const float* __restrict__ b3,
           float* __restrict__ out)
{
    extern __shared__ float sm[];
    float* xt  = sm;            // [RROWS][H]
    float* w1s = sm + 16384;    // [64][260]
    float* h1s = sm + 33024;    // [RROWS][64]
    float* h2t = sm + 37120;    // [64][66]  transposed [k][row]
    float* w3s = sm;            // alias xt
    float* w2s = sm + 16384;    // alias w1s

    const int tid = threadIdx.x;
    const size_t row0 = (size_t)blockIdx.x * RROWS;

    {
        const float4* src = (const float4*)(g_ys + row0 * H);
        float4* dst = (float4*)xt;
        for (int i = tid; i < RROWS * H / 4; i += 256) dst[i] = src[i];
    }
    for (int f = tid; f < H * H1; f += 256) {
        int jj = f & 63; int k = f >> 6;
        w1s[jj * 260 + k] = w1[f];
    }
    __syncthreads();

    const int jp = tid & 31;
    const int rg = tid >> 5;

    // Stage 1
    {
        float acc[8][2];
        #pragma unroll
        for (int i = 0; i < 8; i++) { acc[i][0] = 0.f; acc[i][1] = 0.f; }
        #pragma unroll 4
        for (int k = 0; k < H; k += 4) {
            float4 wa = *(const float4*)&w1s[(2 * jp) * 260 + k];
            float4 wb = *(const float4*)&w1s[(2 * jp + 1) * 260 + k];
            #pragma unroll
            for (int i = 0; i < 8; i++) {
                float4 xv = *(const float4*)&xt[(rg * 8 + i) * H + k];
                acc[i][0] += xv.x * wa.x + xv.y * wa.y + xv.z * wa.z + xv.w * wa.w;
                acc[i][1] += xv.x * wb.x + xv.y * wb.y + xv.z * wb.z + xv.w * wb.w;
            }
        }
        float ba = b1[2 * jp], bb = b1[2 * jp + 1];
        #pragma unroll
        for (int i = 0; i < 8; i++) {
            float va = acc[i][0] + ba; va = va > 0.f ? va : expm1f(va);
            float vb = acc[i][1] + bb; vb = vb > 0.f ? vb : expm1f(vb);
            h1s[(rg * 8 + i) * 64 + 2 * jp]     = va;
            h1s[(rg * 8 + i) * 64 + 2 * jp + 1] = vb;
        }
    }
    __syncthreads();

    for (int f = tid; f < H1 * H2; f += 256) {
        int jj = f & 63; int k = f >> 6;
        w2s[jj * 68 + k] = w2[f];
    }
    __syncthreads();

    // Stage 2 (write h2 transposed)
    {
        float acc[8][2];
        #pragma unroll
        for (int i = 0; i < 8; i++) { acc[i][0] = 0.f; acc[i][1] = 0.f; }
        #pragma unroll
        for (int k = 0; k < H1; k += 4) {
            float4 wa = *(const float4*)&w2s[(2 * jp) * 68 + k];
            float4 wb = *(const float4*)&w2s[(2 * jp + 1) * 68 + k];
            #pragma unroll
            for (int i = 0; i < 8; i++) {
                float4 xv = *(const float4*)&h1s[(rg * 8 + i) * 64 + k];
                acc[i][0] += xv.x * wa.x + xv.y * wa.y + xv.z * wa.z + xv.w * wa.w;
                acc[i][1] += xv.x * wb.x + xv.y * wb.y + xv.z * wb.z + xv.w * wb.w;
            }
        }
        float ba = b2[2 * jp], bb = b2[2 * jp + 1];
        #pragma unroll
        for (int i = 0; i < 8; i++) {
            int row = rg * 8 + i;
            float va = acc[i][0] + ba; va = va > 0.f ? va : expm1f(va);
            float vb = acc[i][1] + bb; vb = vb > 0.f ? vb : expm1f(vb);
            h2t[(2 * jp) * 66 + row]     = va;
            h2t[(2 * jp + 1) * 66 + row] = vb;
        }
    }
    __syncthreads();

    // Stage 3: packed fp32x2 over row pairs
    const int cp  = tid & 31;
    const int rg3 = tid >> 5;

    for (int c0 = 0; c0 < OUTD; c0 += 128) {
        for (int f = tid; f < 64 * 128; f += 256) {
            int c = f & 127; int k = f >> 7;
            int cg = c0 + c;
            w3s[k * 128 + c] = (cg < OUTD) ? w3[(size_t)k * OUTD + cg] : 0.f;
        }
        __syncthreads();

        u64 acc[4][4];
        #pragma unroll
        for (int rp = 0; rp < 4; rp++)
            #pragma unroll
            for (int q = 0; q < 4; q++) acc[rp][q] = 0ull;

        #pragma unroll 4
        for (int k = 0; k < H2; k++) {
            u64 wd[4];
            #pragma unroll
            for (int q = 0; q < 4; q++) {
                float w = w3s[k * 128 + cp + 32 * q];
                wd[q] = pack2(w, w);
            }
            const float* hp = &h2t[k * 66 + rg3 * 8];
            u64 hv0 = *(const u64*)(hp + 0);
            u64 hv1 = *(const u64*)(hp + 2);
            u64 hv2 = *(const u64*)(hp + 4);
            u64 hv3 = *(const u64*)(hp + 6);
            #pragma unroll
            for (int q = 0; q < 4; q++) {
                acc[0][q] = ffma2(hv0, wd[q], acc[0][q]);
                acc[1][q] = ffma2(hv1, wd[q], acc[1][q]);
                acc[2][q] = ffma2(hv2, wd[q], acc[2][q]);
                acc[3][q] = ffma2(hv3, wd[q], acc[3][q]);
            }
        }

        #pragma unroll
        for (int q = 0; q < 4; q++) {
            int cg = c0 + cp + 32 * q;
            if (cg < OUTD) {
                float bq = b3[cg];
                #pragma unroll
                for (int rp = 0; rp < 4; rp++) {
                    float2 v = unpack2(acc[rp][q]);
                    size_t row = row0 + rg3 * 8 + 2 * rp;
                    out[row * OUTD + cg]       = v.x + bq;
                    out[(row + 1) * OUTD + cg] = v.y + bq;
                }
            }
        }
        __syncthreads();
    }
}

__global__ void copy_h_kernel(float* __restrict__ out)
{
    int i = blockIdx.x * blockDim.x + threadIdx.x;
    if (i < B * H / 4) {
        const float4* src = (const float4*)(g_ys + (size_t)(T - 1) * B * H);
        ((float4*)out)[i] = src[i];
    }
}

// ---------------------------------------------------------------------------
extern "C" void kernel_launch(void* const* d_in, const int* in_sizes, int n_in,
                              void* d_out, int out_size)
{
    const float* x    = (const float*)d_in[0];
    const float* h0   = (const float*)d_in[1];
    const float* w_ih = (const float*)d_in[2];
    const float* w_hh = (const float*)d_in[3];
    const float* b_ih = (const float*)d_in[4];
    const float* b_hh = (const float*)d_in[5];
    const float* w1   = (const float*)d_in[6];
    const float* b1   = (const float*)d_in[7];
    const float* w2   = (const float*)d_in[8];
    const float* b2   = (const float*)d_in[9];
    const float* w3   = (const float*)d_in[10];
    const float* b3   = (const float*)d_in[11];
    float* out = (float*)d_out;

    cudaFuncSetAttribute(gru_persist,
                         cudaFuncAttributeMaxDynamicSharedMemorySize, GRU_SMEM);
    cudaFuncSetAttribute(mlp_kernel,
                         cudaFuncAttributeMaxDynamicSharedMemorySize, MLP_SMEM);

    prep_w_kernel<<<(3 * H * H + 255) / 256, 256>>>(w_hh);

    gru_persist<<<NBLK, 256, GRU_SMEM>>>(h0, x, w_ih, b_ih, b_hh);

    mlp_kernel<<<(T * B) / RROWS, 256, MLP_SMEM>>>(w1, b1, w2, b2, w3, b3, out);

    copy_h_kernel<<<(B * H / 4 + 255) / 256, 256>>>(out + (size_t)T * B * OUTD);
}

// round 6
// speedup vs baseline: 2.1556x; 1.0412x over previous
#include <cuda_runtime.h>
#include <cuda_bf16.h>
#include <math.h>
#include <string.h>

typedef unsigned int u32;
typedef unsigned long long u64;

// ---------------------------------------------------------------------------
// Problem constants
// ---------------------------------------------------------------------------
constexpr int T    = 64;
constexpr int B    = 2048;
constexpr int H    = 256;
constexpr int H1   = 64;
constexpr int H2   = 64;
constexpr int OUTD = 601;

// ---------------------------------------------------------------------------
// PTX helpers
// ---------------------------------------------------------------------------
__device__ __forceinline__ u32 smem_u32(const void* p) {
    u32 a;
    asm("{ .reg .u64 t; cvta.to.shared.u64 t, %1; cvt.u32.u64 %0, t; }"
        : "=r"(a) : "l"(p));
    return a;
}
__device__ __forceinline__ void ldsm_x4(u32& r0, u32& r1, u32& r2, u32& r3, u32 addr) {
    asm volatile("ldmatrix.sync.aligned.m8n8.x4.shared.b16 {%0,%1,%2,%3}, [%4];"
                 : "=r"(r0), "=r"(r1), "=r"(r2), "=r"(r3) : "r"(addr));
}
__device__ __forceinline__ void mma_bf16(float* d, const u32* a, const u32* b) {
    asm volatile(
        "mma.sync.aligned.m16n8k16.row.col.f32.bf16.bf16.f32 "
        "{%0,%1,%2,%3}, {%4,%5,%6,%7}, {%8,%9}, {%0,%1,%2,%3};"
        : "+f"(d[0]), "+f"(d[1]), "+f"(d[2]), "+f"(d[3])
        : "r"(a[0]), "r"(a[1]), "r"(a[2]), "r"(a[3]), "r"(b[0]), "r"(b[1]));
}
__device__ __forceinline__ void cp16(u32 dst, const void* src) {
    asm volatile("cp.async.ca.shared.global [%0], [%1], 16;" :: "r"(dst), "l"(src));
}
__device__ __forceinline__ void cp_wait_all() {
    asm volatile("cp.async.wait_all;" ::: "memory");
}
__device__ __forceinline__ u32 bf2u(__nv_bfloat162 v) {
    u32 r; memcpy(&r, &v, 4); return r;
}
// fp32x2 packed math for MLP stage-3
__device__ __forceinline__ u64 ffma2(u64 a, u64 b, u64 c) {
    u64 d; asm("fma.rn.f32x2 %0, %1, %2, %3;" : "=l"(d) : "l"(a), "l"(b), "l"(c));
    return d;
}
__device__ __forceinline__ u64 pack2(float x, float y) {
    u64 d; asm("mov.b64 %0, {%1, %2};" : "=l"(d) : "f"(x), "f"(y));
    return d;
}
__device__ __forceinline__ float2 unpack2(u64 v) {
    float2 r; asm("mov.b64 {%0, %1}, %2;" : "=f"(r.x), "=f"(r.y) : "l"(v));
    return r;
}

// ---------------------------------------------------------------------------
// Device scratch
// ---------------------------------------------------------------------------
__device__ float g_ys[(size_t)T * B * H];              // hidden states (MLP input)
__device__ __nv_bfloat16 g_whi[(size_t)3 * H * H];     // w_hh split hi
__device__ __nv_bfloat16 g_wlo[(size_t)3 * H * H];     // w_hh split lo
__device__ u32 g_hhi[(size_t)B * H / 2];               // h as bf16x2 hi (ping state)
__device__ u32 g_hlo[(size_t)B * H / 2];               // h as bf16x2 lo
// per-bg 4-block barriers (128B apart)
__device__ u32 g_cnt[32 * 32];
__device__ u32 g_gen[32 * 32];

__global__ void prep_w_kernel(const float* __restrict__ w_hh)
{
    int i = blockIdx.x * blockDim.x + threadIdx.x;
    if (i < 3 * H * H) {
        float w = w_hh[i];
        __nv_bfloat16 hi = __float2bfloat16(w);
        g_whi[i] = hi;
        g_wlo[i] = __float2bfloat16(w - __bfloat162float(hi));
    }
}

// ---------------------------------------------------------------------------
// Persistent GRU: 128 blocks (4 j-chunks x 32 batch-groups), 512 threads,
// 4x4 warp tiling. Weights in smem once; h state in registers; h exchanged
// between the 4 sibling blocks as pre-split bf16 via global; 4-block barrier.
// ---------------------------------------------------------------------------
constexpr int NBLK = 128;
constexpr int SM_W     = 0;        // whi [4][192][128B] = 98304 ; wlo at +98304
constexpr int SM_WLO_O = 98304;
constexpr int SM_A     = 196608;   // 2 bufs x (hi 8192 + lo 8192) = 32768
constexpr int SM_PRM   = 229376;   // 7*64 f32 = 1792
constexpr int GRU_SMEM = 231168;

__global__ void __launch_bounds__(512, 1)
gru_persist(const float* __restrict__ h0,
            const float* __restrict__ x,
            const float* __restrict__ w_ih,
            const float* __restrict__ b_ih,
            const float* __restrict__ b_hh)
{
    extern __shared__ char smem[];
    const u32 sb = smem_u32(smem);
    float* sparam = (float*)(smem + SM_PRM);

    const int tid  = threadIdx.x;
    const int wid  = tid >> 5;
    const int lane = tid & 31;
    const int jc = blockIdx.x & 3;
    const int bg = blockIdx.x >> 2;
    const int j0 = jc * 64;
    const int b0 = bg * 64;
    const int wm = wid >> 2;   // 0..3 : 16 batch rows
    const int wn = wid & 3;    // 0..3 : 16 j cols (x3 gates)

    u32 gen0 = 0;
    if (tid == 0) gen0 = atomicAdd(&g_gen[bg * 32], 0);

    if (tid < 64) {
        int jg = j0 + tid;
        sparam[tid]        = w_ih[jg];
        sparam[64 + tid]   = w_ih[H + jg];
        sparam[128 + tid]  = w_ih[2 * H + jg];
        sparam[192 + tid]  = b_ih[jg]         + b_hh[jg];
        sparam[256 + tid]  = b_ih[H + jg]     + b_hh[H + jg];
        sparam[320 + tid]  = b_ih[2 * H + jg];
        sparam[384 + tid]  = b_hh[2 * H + jg];
    }

    // Stage all weights once (bf16 hi/lo, SW128): [c][rr=g*64+jj][128B]
    for (int c = 0; c < 4; c++) {
        for (int f = tid; f < 192 * 8; f += 512) {
            int rr = f >> 3, cc = f & 7;
            int g = rr >> 6, jj = rr & 63;
            size_t src = ((size_t)(g * H + j0 + jj)) * H + c * 64 + cc * 8;
            u32 d = sb + SM_W + c * 24576 + rr * 128 + ((cc * 16) ^ ((rr & 7) << 4));
            cp16(d, g_whi + src);
            cp16(d + SM_WLO_O, g_wlo + src);
        }
    }
    cp_wait_all();
    __syncthreads();

    const int a_row  = lane & 15;
    const int a_colh = (lane >> 4) * 16;
    const int b_row  = ((lane >> 4) << 3) + (lane & 7);
    const int b_colh = ((lane >> 3) & 1) * 16;
    const int l4 = lane >> 2;
    const int lp = lane & 3;

    // register-resident h state for the (b,j) this lane owns in the epilogue
    float2 hst[2][2];
    #pragma unroll
    for (int e = 0; e < 2; e++)
        #pragma unroll
        for (int sub = 0; sub < 2; sub++) {
            int rowg = b0 + wm * 16 + l4 + 8 * e;
            int jl = wn * 16 + 8 * sub + 2 * lp;
            hst[e][sub] = *(const float2*)&h0[(size_t)rowg * H + j0 + jl];
        }

    for (int t = 0; t < T; t++) {
        float* hout = g_ys + (size_t)t * B * H;

        // ---- stage A chunk 0 into buf 0 ----
        if (t == 0) {
            #pragma unroll
            for (int i = 0; i < 4; i++) {
                int f = tid + i * 512;
                int row = f >> 5, kp = f & 31;
                float2 hv = *(const float2*)&h0[(size_t)(b0 + row) * H + 2 * kp];
                __nv_bfloat162 h2 = __floats2bfloat162_rn(hv.x, hv.y);
                __nv_bfloat162 l2 = __floats2bfloat162_rn(hv.x - __bfloat162float(h2.x),
                                                          hv.y - __bfloat162float(h2.y));
                u32 off = (u32)(row * 128) + (u32)((kp * 4) ^ ((row & 7) << 4));
                *(u32*)(smem + SM_A + off)        = bf2u(h2);
                *(u32*)(smem + SM_A + 8192 + off) = bf2u(l2);
            }
        } else {
            #pragma unroll
            for (int i = 0; i < 4; i++) {
                int f = tid + i * 512;
                int row = f >> 5, kp = f & 31;
                size_t gi = (size_t)(b0 + row) * 128 + kp;
                u32 off = (u32)(row * 128) + (u32)((kp * 4) ^ ((row & 7) << 4));
                *(u32*)(smem + SM_A + off)        = g_hhi[gi];
                *(u32*)(smem + SM_A + 8192 + off) = g_hlo[gi];
            }
        }
        __syncthreads();

        float acc[3][2][4];
        #pragma unroll
        for (int g = 0; g < 3; g++)
            #pragma unroll
            for (int s = 0; s < 2; s++)
                #pragma unroll
                for (int q = 0; q < 4; q++) acc[g][s][q] = 0.f;

        for (int c = 0; c < 4; c++) {
            // prefetch next chunk into registers (hidden under MMA)
            float2 pf[4];
            u32 ph[4], pl[4];
            if (c < 3) {
                if (t == 0) {
                    #pragma unroll
                    for (int i = 0; i < 4; i++) {
                        int f = tid + i * 512;
                        pf[i] = *(const float2*)
                            &h0[(size_t)(b0 + (f >> 5)) * H + (c + 1) * 64 + 2 * (f & 31)];
                    }
                } else {
                    #pragma unroll
                    for (int i = 0; i < 4; i++) {
                        int f = tid + i * 512;
                        size_t gi = (size_t)(b0 + (f >> 5)) * 128 + (c + 1) * 32 + (f & 31);
                        ph[i] = g_hhi[gi];
                        pl[i] = g_hlo[gi];
                    }
                }
            }
            const u32 ab = sb + SM_A + (c & 1) * 16384;
            const u32 wb = sb + SM_W + c * 24576;

            #pragma unroll
            for (int ks = 0; ks < 4; ks++) {
                u32 ahi[4], alo[4];
                {
                    int r = wm * 16 + a_row;
                    u32 off = (u32)(r * 128) + (u32)((ks * 32 + a_colh) ^ ((r & 7) << 4));
                    ldsm_x4(ahi[0], ahi[1], ahi[2], ahi[3], ab + off);
                    ldsm_x4(alo[0], alo[1], alo[2], alo[3], ab + 8192 + off);
                }
                #pragma unroll
                for (int g = 0; g < 3; g++) {
                    int rr = g * 64 + wn * 16 + b_row;
                    u32 off = (u32)(rr * 128) + (u32)((ks * 32 + b_colh) ^ ((rr & 7) << 4));
                    u32 bh[4], bl[4];
                    ldsm_x4(bh[0], bh[1], bh[2], bh[3], wb + off);
                    ldsm_x4(bl[0], bl[1], bl[2], bl[3], wb + SM_WLO_O + off);
                    mma_bf16(acc[g][0], ahi, bh);
                    mma_bf16(acc[g][1], ahi, bh + 2);
                    mma_bf16(acc[g][0], ahi, bl);
                    mma_bf16(acc[g][1], ahi, bl + 2);
                    mma_bf16(acc[g][0], alo, bh);
                    mma_bf16(acc[g][1], alo, bh + 2);
                }
            }
            if (c < 3) {
                char* base = smem + SM_A + ((c + 1) & 1) * 16384;
                if (t == 0) {
                    #pragma unroll
                    for (int i = 0; i < 4; i++) {
                        int f = tid + i * 512;
                        int row = f >> 5, kp = f & 31;
                        __nv_bfloat162 h2 = __floats2bfloat162_rn(pf[i].x, pf[i].y);
                        __nv_bfloat162 l2 = __floats2bfloat162_rn(
                            pf[i].x - __bfloat162float(h2.x),
                            pf[i].y - __bfloat162float(h2.y));
                        u32 off = (u32)(row * 128) + (u32)((kp * 4) ^ ((row & 7) << 4));
                        *(u32*)(base + off)        = bf2u(h2);
                        *(u32*)(base + 8192 + off) = bf2u(l2);
                    }
                } else {
                    #pragma unroll
                    for (int i = 0; i < 4; i++) {
                        int f = tid + i * 512;
                        int row = f >> 5, kp = f & 31;
                        u32 off = (u32)(row * 128) + (u32)((kp * 4) ^ ((row & 7) << 4));
                        *(u32*)(base + off)        = ph[i];
                        *(u32*)(base + 8192 + off) = pl[i];
                    }
                }
            }
            __syncthreads();
        }

        // ---- register epilogue: gate math, update h regs, emit fp32 + bf16 ----
        #pragma unroll
        for (int e = 0; e < 2; e++) {
            int rowg = b0 + wm * 16 + l4 + 8 * e;
            float xv = x[(size_t)t * B + rowg];
            #pragma unroll
            for (int sub = 0; sub < 2; sub++) {
                int jl = wn * 16 + 8 * sub + 2 * lp;
                float hn0, hn1;
                {
                    int j = jl;
                    float r = 1.f / (1.f + expf(-(xv * sparam[j] + sparam[192 + j]
                                                  + acc[0][sub][e * 2])));
                    float z = 1.f / (1.f + expf(-(xv * sparam[64 + j] + sparam[256 + j]
                                                  + acc[1][sub][e * 2])));
                    float n = tanhf(xv * sparam[128 + j] + sparam[320 + j]
                                    + r * (acc[2][sub][e * 2] + sparam[384 + j]));
                    hn0 = (1.f - z) * n + z * hst[e][sub].x;
                }
                {
                    int j = jl + 1;
                    float r = 1.f / (1.f + expf(-(xv * sparam[j] + sparam[192 + j]
                                                  + acc[0][sub][e * 2 + 1])));
                    float z = 1.f / (1.f + expf(-(xv * sparam[64 + j] + sparam[256 + j]
                                                  + acc[1][sub][e * 2 + 1])));
                    float n = tanhf(xv * sparam[128 + j] + sparam[320 + j]
                                    + r * (acc[2][sub][e * 2 + 1] + sparam[384 + j]));
                    hn1 = (1.f - z) * n + z * hst[e][sub].y;
                }
                hst[e][sub] = make_float2(hn0, hn1);
                *(float2*)&hout[(size_t)rowg * H + j0 + jl] = hst[e][sub];
                __nv_bfloat162 h2 = __floats2bfloat162_rn(hn0, hn1);
                __nv_bfloat162 l2 = __floats2bfloat162_rn(hn0 - __bfloat162float(h2.x),
                                                          hn1 - __bfloat162float(h2.y));
                size_t gi = (size_t)rowg * 128 + jc * 32 + wn * 8 + 4 * sub + lp;
                g_hhi[gi] = bf2u(h2);
                g_hlo[gi] = bf2u(l2);
            }
        }

        // ---- 4-block barrier within this batch group ----
        if (t < T - 1) {
            __threadfence();
            __syncthreads();
            if (tid == 0) {
                u32 target = gen0 + (u32)t + 1u;
                u32 old = atomicAdd(&g_cnt[bg * 32], 1u);
                if (old == 3u) {
                    atomicExch(&g_cnt[bg * 32], 0u);
                    __threadfence();
                    atomicExch(&g_gen[bg * 32], target);
                } else {
                    u32 g;
                    do {
                        asm volatile("ld.acquire.gpu.global.u32 %0, [%1];"
                                     : "=r"(g) : "l"(&g_gen[bg * 32]));
                    } while ((int)(g - target) < 0);
                }
            }
            __syncthreads();
        }
    }
}

// ---------------------------------------------------------------------------
// Fused MLP (R2 version): fp32, fp32x2 in stage 3.
// ---------------------------------------------------------------------------
constexpr int RROWS = 64;
constexpr int MLP_SMEM = (16384 + 16640 + 4096 + 4224) * 4;

__global__ void __launch_bounds__(256)
mlp_kernel(const float* __restrict__ w1, const float* __restrict__ b1,
           const float* __restrict__ w2, const float* __restrict__ b2,
           const float* __restrict__ w3, const float* __restrict__ b3,
           float* __restrict__ out)
{
    extern __shared__ float sm[];
    float* xt  = sm;
    float* w1s = sm + 16384;
    float* h1s = sm + 33024;
    float* h2t = sm + 37120;
    float* w3s = sm;
    float* w2s = sm + 16384;

    const int tid = threadIdx.x;
    const size_t row0 = (size_t)blockIdx.x * RROWS;

    {
        const float4* src = (const float4*)(g_ys + row0 * H);
        float4* dst = (float4*)xt;
        for (int i = tid; i < RROWS * H / 4; i += 256) dst[i] = src[i];
    }
    for (int f = tid; f < H * H1; f += 256) {
        int jj = f & 63; int k = f >> 6;
        w1s[jj * 260 + k] = w1[f];
    }
    __syncthreads();

    const int jp = tid & 31;
    const int rg = tid >> 5;

    // Stage 1
    {
        float acc[8][2];
        #pragma unroll
        for (int i = 0; i < 8; i++) { acc[i][0] = 0.f; acc[i][1] = 0.f; }
        #pragma unroll 4
        for (int k = 0; k < H; k += 4) {
            float4 wa = *(const float4*)&w1s[(2 * jp) * 260 + k];
            float4 wb = *(const float4*)&w1s[(2 * jp + 1) * 260 + k];
            #pragma unroll
            for (int i = 0; i < 8; i++) {
                float4 xv = *(const float4*)&xt[(rg * 8 + i) * H + k];
                acc[i][0] += xv.x * wa.x + xv.y * wa.y + xv.z * wa.z + xv.w * wa.w;
                acc[i][1] += xv.x * wb.x + xv.y * wb.y + xv.z * wb.z + xv.w * wb.w;
            }
        }
        float ba = b1[2 * jp], bb = b1[2 * jp + 1];
        #pragma unroll
        for (int i = 0; i < 8; i++) {
            float va = acc[i][0] + ba; va = va > 0.f ? va : expm1f(va);
            float vb = acc[i][1] + bb; vb = vb > 0.f ? vb : expm1f(vb);
            h1s[(rg * 8 + i) * 64 + 2 * jp]     = va;
            h1s[(rg * 8 + i) * 64 + 2 * jp + 1] = vb;
        }
    }
    __syncthreads();

    for (int f = tid; f < H1 * H2; f += 256) {
        int jj = f & 63; int k = f >> 6;
        w2s[jj * 68 + k] = w2[f];
    }
    __syncthreads();

    // Stage 2 (h2 transposed)
    {
        float acc[8][2];
        #pragma unroll
        for (int i = 0; i < 8; i++) { acc[i][0] = 0.f; acc[i][1] = 0.f; }
        #pragma unroll
        for (int k = 0; k < H1; k += 4) {
            float4 wa = *(const float4*)&w2s[(2 * jp) * 68 + k];
            float4 wb = *(const float4*)&w2s[(2 * jp + 1) * 68 + k];
            #pragma unroll
            for (int i = 0; i < 8; i++) {
                float4 xv = *(const float4*)&h1s[(rg * 8 + i) * 64 + k];
                acc[i][0] += xv.x * wa.x + xv.y * wa.y + xv.z * wa.z + xv.w * wa.w;
                acc[i][1] += xv.x * wb.x + xv.y * wb.y + xv.z * wb.z + xv.w * wb.w;
            }
        }
        float ba = b2[2 * jp], bb = b2[2 * jp + 1];
        #pragma unroll
        for (int i = 0; i < 8; i++) {
            int row = rg * 8 + i;
            float va = acc[i][0] + ba; va = va > 0.f ? va : expm1f(va);
            float vb = acc[i][1] + bb; vb = vb > 0.f ? vb : expm1f(vb);
            h2t[(2 * jp) * 66 + row]     = va;
            h2t[(2 * jp + 1) * 66 + row] = vb;
        }
    }
    __syncthreads();

    // Stage 3: packed fp32x2
    const int cp  = tid & 31;
    const int rg3 = tid >> 5;

    for (int c0 = 0; c0 < OUTD; c0 += 128) {
        for (int f = tid; f < 64 * 128; f += 256) {
            int c = f & 127; int k = f >> 7;
            int cg = c0 + c;
            w3s[k * 128 + c] = (cg < OUTD) ? w3[(size_t)k * OUTD + cg] : 0.f;
        }
        __syncthreads();

        u64 acc[4][4];
        #pragma unroll
        for (int rp = 0; rp < 4; rp++)
            #pragma unroll
            for (int q = 0; q < 4; q++) acc[rp][q] = 0ull;

        #pragma unroll 4
        for (int k = 0; k < H2; k++) {
            u64 wd[4];
            #pragma unroll
            for (int q = 0; q < 4; q++) {
                float w = w3s[k * 128 + cp + 32 * q];
                wd[q] = pack2(w, w);
            }
            const float* hp = &h2t[k * 66 + rg3 * 8];
            u64 hv0 = *(const u64*)(hp + 0);
            u64 hv1 = *(const u64*)(hp + 2);
            u64 hv2 = *(const u64*)(hp + 4);
            u64 hv3 = *(const u64*)(hp + 6);
            #pragma unroll
            for (int q = 0; q < 4; q++) {
                acc[0][q] = ffma2(hv0, wd[q], acc[0][q]);
                acc[1][q] = ffma2(hv1, wd[q], acc[1][q]);
                acc[2][q] = ffma2(hv2, wd[q], acc[2][q]);
                acc[3][q] = ffma2(hv3, wd[q], acc[3][q]);
            }
        }

        #pragma unroll
        for (int q = 0; q < 4; q++) {
            int cg = c0 + cp + 32 * q;
            if (cg < OUTD) {
                float bq = b3[cg];
                #pragma unroll
                for (int rp = 0; rp < 4; rp++) {
                    float2 v = unpack2(acc[rp][q]);
                    size_t row = row0 + rg3 * 8 + 2 * rp;
                    out[row * OUTD + cg]       = v.x + bq;
                    out[(row + 1) * OUTD + cg] = v.y + bq;
                }
            }
        }
        __syncthreads();
    }
}

__global__ void copy_h_kernel(float* __restrict__ out)
{
    int i = blockIdx.x * blockDim.x + threadIdx.x;
    if (i < B * H / 4) {
        const float4* src = (const float4*)(g_ys + (size_t)(T - 1) * B * H);
        ((float4*)out)[i] = src[i];
    }
}

// ---------------------------------------------------------------------------
extern "C" void kernel_launch(void* const* d_in, const int* in_sizes, int n_in,
                              void* d_out, int out_size)
{
    const float* x    = (const float*)d_in[0];
    const float* h0   = (const float*)d_in[1];
    const float* w_ih = (const float*)d_in[2];
    const float* w_hh = (const float*)d_in[3];
    const float* b_ih = (const float*)d_in[4];
    const float* b_hh = (const float*)d_in[5];
    const float* w1   = (const float*)d_in[6];
    const float* b1   = (const float*)d_in[7];
    const float* w2   = (const float*)d_in[8];
    const float* b2   = (const float*)d_in[9];
    const float* w3   = (const float*)d_in[10];
    const float* b3   = (const float*)d_in[11];
    float* out = (float*)d_out;

    cudaFuncSetAttribute(gru_persist,
                         cudaFuncAttributeMaxDynamicSharedMemorySize, GRU_SMEM);
    cudaFuncSetAttribute(mlp_kernel,
                         cudaFuncAttributeMaxDynamicSharedMemorySize, MLP_SMEM);

    prep_w_kernel<<<(3 * H * H + 255) / 256, 256>>>(w_hh);

    gru_persist<<<NBLK, 512, GRU_SMEM>>>(h0, x, w_ih, b_ih, b_hh);

    mlp_kernel<<<(T * B) / RROWS, 256, MLP_SMEM>>>(w1, b1, w2, b2, w3, b3, out);

    copy_h_kernel<<<(B * H / 4 + 255) / 256, 256>>>(out + (size_t)T * B * OUTD);
}

// round 7
// speedup vs baseline: 2.2898x; 1.0622x over previous
#include <cuda_runtime.h>
#include <cuda_bf16.h>
#include <math.h>
#include <string.h>

typedef unsigned int u32;
typedef unsigned long long u64;

// ---------------------------------------------------------------------------
// Problem constants
// ---------------------------------------------------------------------------
constexpr int T    = 64;
constexpr int B    = 2048;
constexpr int H    = 256;
constexpr int H1   = 64;
constexpr int H2   = 64;
constexpr int OUTD = 601;

// ---------------------------------------------------------------------------
// PTX helpers
// ---------------------------------------------------------------------------
__device__ __forceinline__ u32 smem_u32(const void* p) {
    u32 a;
    asm("{ .reg .u64 t; cvta.to.shared.u64 t, %1; cvt.u32.u64 %0, t; }"
        : "=r"(a) : "l"(p));
    return a;
}
__device__ __forceinline__ void ldsm_x4(u32& r0, u32& r1, u32& r2, u32& r3, u32 addr) {
    asm volatile("ldmatrix.sync.aligned.m8n8.x4.shared.b16 {%0,%1,%2,%3}, [%4];"
                 : "=r"(r0), "=r"(r1), "=r"(r2), "=r"(r3) : "r"(addr));
}
__device__ __forceinline__ void mma_bf16(float* d, const u32* a, const u32* b) {
    asm volatile(
        "mma.sync.aligned.m16n8k16.row.col.f32.bf16.bf16.f32 "
        "{%0,%1,%2,%3}, {%4,%5,%6,%7}, {%8,%9}, {%0,%1,%2,%3};"
        : "+f"(d[0]), "+f"(d[1]), "+f"(d[2]), "+f"(d[3])
        : "r"(a[0]), "r"(a[1]), "r"(a[2]), "r"(a[3]), "r"(b[0]), "r"(b[1]));
}
__device__ __forceinline__ void cp16(u32 dst, const void* src) {
    asm volatile("cp.async.ca.shared.global [%0], [%1], 16;" :: "r"(dst), "l"(src));
}
__device__ __forceinline__ void cp_wait_all() {
    asm volatile("cp.async.wait_all;" ::: "memory");
}
__device__ __forceinline__ u32 bf2u(__nv_bfloat162 v) {
    u32 r; memcpy(&r, &v, 4); return r;
}
// fp32x2 packed math for MLP stage-3
__device__ __forceinline__ u64 ffma2(u64 a, u64 b, u64 c) {
    u64 d; asm("fma.rn.f32x2 %0, %1, %2, %3;" : "=l"(d) : "l"(a), "l"(b), "l"(c));
    return d;
}
__device__ __forceinline__ u64 pack2(float x, float y) {
    u64 d; asm("mov.b64 %0, {%1, %2};" : "=l"(d) : "f"(x), "f"(y));
    return d;
}
__device__ __forceinline__ float2 unpack2(u64 v) {
    float2 r; asm("mov.b64 {%0, %1}, %2;" : "=f"(r.x), "=f"(r.y) : "l"(v));
    return r;
}
// ---- fast MUFU-based activations (err ~1e-6, budget 1e-3) ----
constexpr float LOG2E  = 1.4426950408889634f;
__device__ __forceinline__ float fast_sigmoid(float v) {
    float e; asm("ex2.approx.f32 %0, %1;" : "=f"(e) : "f"(-LOG2E * v));
    float r; asm("rcp.approx.f32 %0, %1;" : "=f"(r) : "f"(1.f + e));
    return r;
}
__device__ __forceinline__ float fast_tanh(float v) {
    float e; asm("ex2.approx.f32 %0, %1;" : "=f"(e) : "f"(2.f * LOG2E * v));
    float r; asm("rcp.approx.f32 %0, %1;" : "=f"(r) : "f"(1.f + e));
    return 1.f - 2.f * r;
}
__device__ __forceinline__ float fast_elu(float v) {
    if (v > 0.f) return v;
    float e; asm("ex2.approx.f32 %0, %1;" : "=f"(e) : "f"(LOG2E * v));
    return e - 1.f;
}

// ---------------------------------------------------------------------------
// Device scratch
// ---------------------------------------------------------------------------
__device__ float g_ys[(size_t)T * B * H];              // hidden states (MLP input)
__device__ __nv_bfloat16 g_whi[(size_t)3 * H * H];     // w_hh split hi
__device__ __nv_bfloat16 g_wlo[(size_t)3 * H * H];     // w_hh split lo
__device__ u32 g_hhi[(size_t)B * H / 2];               // h as bf16x2 hi
__device__ u32 g_hlo[(size_t)B * H / 2];               // h as bf16x2 lo
__device__ u32 g_cnt[32 * 32];                         // per-bg barriers, 128B apart
__device__ u32 g_gen[32 * 32];

__global__ void prep_w_kernel(const float* __restrict__ w_hh)
{
    int i = blockIdx.x * blockDim.x + threadIdx.x;
    if (i < 3 * H * H) {
        float w = w_hh[i];
        __nv_bfloat16 hi = __float2bfloat16(w);
        g_whi[i] = hi;
        g_wlo[i] = __float2bfloat16(w - __bfloat162float(hi));
    }
}

// ---------------------------------------------------------------------------
// Persistent GRU. 128 blocks (4 j-chunks x 32 batch groups), 512 threads.
// Own j-chunk of A is written to smem by the epilogue -> next step's MMA on it
// starts before the sibling barrier resolves.
// ---------------------------------------------------------------------------
constexpr int NBLK = 128;
constexpr int SM_W     = 0;        // whi [4][192][128B] = 98304 ; wlo at +98304
constexpr int SM_WLO_O = 98304;
constexpr int SM_A     = 196608;   // 2 bufs x (hi 8192 + lo 8192) = 32768
constexpr int SM_PRM   = 229376;   // 7*64 f32
constexpr int GRU_SMEM = 231168;

struct AccT { float a[3][2][4]; };

__device__ __forceinline__ void mma_section(AccT& A, u32 ab, u32 wb,
                                            int wm, int wn,
                                            int a_row, int a_colh,
                                            int b_row, int b_colh)
{
    #pragma unroll
    for (int ks = 0; ks < 4; ks++) {
        u32 ahi[4], alo[4];
        {
            int r = wm * 16 + a_row;
            u32 off = (u32)(r * 128) + (u32)((ks * 32 + a_colh) ^ ((r & 7) << 4));
            ldsm_x4(ahi[0], ahi[1], ahi[2], ahi[3], ab + off);
            ldsm_x4(alo[0], alo[1], alo[2], alo[3], ab + 8192 + off);
        }
        #pragma unroll
        for (int g = 0; g < 3; g++) {
            int rr = g * 64 + wn * 16 + b_row;
            u32 off = (u32)(rr * 128) + (u32)((ks * 32 + b_colh) ^ ((rr & 7) << 4));
            u32 bh[4], bl[4];
            ldsm_x4(bh[0], bh[1], bh[2], bh[3], wb + off);
            ldsm_x4(bl[0], bl[1], bl[2], bl[3], wb + SM_WLO_O + off);
            mma_bf16(A.a[g][0], ahi, bh);
            mma_bf16(A.a[g][1], ahi, bh + 2);
            mma_bf16(A.a[g][0], ahi, bl);
            mma_bf16(A.a[g][1], ahi, bl + 2);
            mma_bf16(A.a[g][0], alo, bh);
            mma_bf16(A.a[g][1], alo, bh + 2);
        }
    }
}

__global__ void __launch_bounds__(512, 1)
gru_persist(const float* __restrict__ h0,
            const float* __restrict__ x,
            const float* __restrict__ w_ih,
            const float* __restrict__ b_ih,
            const float* __restrict__ b_hh)
{
    extern __shared__ char smem[];
    const u32 sb = smem_u32(smem);
    float* sparam = (float*)(smem + SM_PRM);

    const int tid  = threadIdx.x;
    const int wid  = tid >> 5;
    const int lane = tid & 31;
    const int jc = blockIdx.x & 3;
    const int bg = blockIdx.x >> 2;
    const int j0 = jc * 64;
    const int b0 = bg * 64;
    const int wm = wid >> 2;
    const int wn = wid & 3;

    const u32 gen0 = g_gen[bg * 32];   // stable: no sibling can flip gen before
                                       // its own first read (see barrier proto)

    if (tid < 64) {
        int jg = j0 + tid;
        sparam[tid]        = w_ih[jg];
        sparam[64 + tid]   = w_ih[H + jg];
        sparam[128 + tid]  = w_ih[2 * H + jg];
        sparam[192 + tid]  = b_ih[jg]         + b_hh[jg];
        sparam[256 + tid]  = b_ih[H + jg]     + b_hh[H + jg];
        sparam[320 + tid]  = b_ih[2 * H + jg];
        sparam[384 + tid]  = b_hh[2 * H + jg];
    }

    // Stage all weights once (bf16 hi/lo, SW128): [c][rr=g*64+jj][128B]
    for (int c = 0; c < 4; c++) {
        for (int f = tid; f < 192 * 8; f += 512) {
            int rr = f >> 3, cc = f & 7;
            int g = rr >> 6, jj = rr & 63;
            size_t src = ((size_t)(g * H + j0 + jj)) * H + c * 64 + cc * 8;
            u32 d = sb + SM_W + c * 24576 + rr * 128 + ((cc * 16) ^ ((rr & 7) << 4));
            cp16(d, g_whi + src);
            cp16(d + SM_WLO_O, g_wlo + src);
        }
    }

    const int a_row  = lane & 15;
    const int a_colh = (lane >> 4) * 16;
    const int b_row  = ((lane >> 4) << 3) + (lane & 7);
    const int b_colh = ((lane >> 3) & 1) * 16;
    const int l4 = lane >> 2;
    const int lp = lane & 3;

    // register-resident h state for this lane's (b,j) ownership
    float2 hst[2][2];
    #pragma unroll
    for (int e = 0; e < 2; e++)
        #pragma unroll
        for (int sub = 0; sub < 2; sub++) {
            int rowg = b0 + wm * 16 + l4 + 8 * e;
            int jl = wn * 16 + 8 * sub + 2 * lp;
            hst[e][sub] = *(const float2*)&h0[(size_t)rowg * H + j0 + jl];
        }

    // pre-stage OWN chunk (c=jc) of h0 into buf0
    #pragma unroll
    for (int i = 0; i < 4; i++) {
        int f = tid + i * 512;
        int row = f >> 5, kp = f & 31;
        float2 hv = *(const float2*)&h0[(size_t)(b0 + row) * H + jc * 64 + 2 * kp];
        __nv_bfloat162 h2 = __floats2bfloat162_rn(hv.x, hv.y);
        __nv_bfloat162 l2 = __floats2bfloat162_rn(hv.x - __bfloat162float(h2.x),
                                                  hv.y - __bfloat162float(h2.y));
        u32 off = (u32)(row * 128) + (u32)((kp * 4) ^ ((row & 7) << 4));
        *(u32*)(smem + SM_A + off)        = bf2u(h2);
        *(u32*)(smem + SM_A + 8192 + off) = bf2u(l2);
    }
    cp_wait_all();
    __syncthreads();

    const u32 ab0 = sb + SM_A;
    const u32 ab1 = sb + SM_A + 16384;

    for (int t = 0; t < T; t++) {
        float* hout = g_ys + (size_t)t * B * H;

        // prefetch x for this step (2 rows per lane)
        float xv0 = x[(size_t)t * B + b0 + wm * 16 + l4];
        float xv1 = x[(size_t)t * B + b0 + wm * 16 + l4 + 8];

        AccT A;
        #pragma unroll
        for (int g = 0; g < 3; g++)
            #pragma unroll
            for (int s = 0; s < 2; s++)
                #pragma unroll
                for (int q = 0; q < 4; q++) A.a[g][s][q] = 0.f;

        // ---- MMA on OWN chunk first (buf0; no barrier needed) ----
        mma_section(A, ab0, sb + SM_W + jc * 24576, wm, wn, a_row, a_colh, b_row, b_colh);

        // ---- wait for siblings' h_{t-1} (overlapped: release usually done) ----
        if (t > 0) {
            u32 target = gen0 + (u32)t;
            u32 g;
            do {
                asm volatile("ld.acquire.gpu.global.u32 %0, [%1];"
                             : "=r"(g) : "l"(&g_gen[bg * 32]));
            } while ((int)(g - target) < 0);
        }

        // ---- stage chunk jc+1 into buf1 ----
        {
            int c = (jc + 1) & 3;
            if (t == 0) {
                #pragma unroll
                for (int i = 0; i < 4; i++) {
                    int f = tid + i * 512;
                    int row = f >> 5, kp = f & 31;
                    float2 hv = *(const float2*)&h0[(size_t)(b0 + row) * H + c * 64 + 2 * kp];
                    __nv_bfloat162 h2 = __floats2bfloat162_rn(hv.x, hv.y);
                    __nv_bfloat162 l2 = __floats2bfloat162_rn(hv.x - __bfloat162float(h2.x),
                                                              hv.y - __bfloat162float(h2.y));
                    u32 off = (u32)(row * 128) + (u32)((kp * 4) ^ ((row & 7) << 4));
                    *(u32*)(smem + SM_A + 16384 + off)        = bf2u(h2);
                    *(u32*)(smem + SM_A + 16384 + 8192 + off) = bf2u(l2);
                }
            } else {
                #pragma unroll
                for (int i = 0; i < 4; i++) {
                    int f = tid + i * 512;
                    int row = f >> 5, kp = f & 31;
                    size_t gi = (size_t)(b0 + row) * 128 + c * 32 + kp;
                    u32 off = (u32)(row * 128) + (u32)((kp * 4) ^ ((row & 7) << 4));
                    *(u32*)(smem + SM_A + 16384 + off)        = g_hhi[gi];
                    *(u32*)(smem + SM_A + 16384 + 8192 + off) = g_hlo[gi];
                }
            }
        }
        __syncthreads();

        // ---- remaining chunks, double-buffered with register prefetch ----
        #pragma unroll
        for (int i = 1; i <= 3; i++) {
            int c  = (jc + i) & 3;
            int cn = (jc + i + 1) & 3;
            u32 ab = (i & 1) ? ab1 : ab0;

            float2 pf[4];
            u32 ph[4], pl[4];
            if (i < 3) {
                if (t == 0) {
                    #pragma unroll
                    for (int k = 0; k < 4; k++) {
                        int f = tid + k * 512;
                        pf[k] = *(const float2*)
                            &h0[(size_t)(b0 + (f >> 5)) * H + cn * 64 + 2 * (f & 31)];
                    }
                } else {
                    #pragma unroll
                    for (int k = 0; k < 4; k++) {
                        int f = tid + k * 512;
                        size_t gi = (size_t)(b0 + (f >> 5)) * 128 + cn * 32 + (f & 31);
                        ph[k] = g_hhi[gi];
                        pl[k] = g_hlo[gi];
                    }
                }
            }

            mma_section(A, ab, sb + SM_W + c * 24576, wm, wn, a_row, a_colh, b_row, b_colh);

            if (i < 3) {
                char* base = smem + SM_A + ((i & 1) ? 0 : 16384);
                if (t == 0) {
                    #pragma unroll
                    for (int k = 0; k < 4; k++) {
                        int f = tid + k * 512;
                        int row = f >> 5, kp = f & 31;
                        __nv_bfloat162 h2 = __floats2bfloat162_rn(pf[k].x, pf[k].y);
                        __nv_bfloat162 l2 = __floats2bfloat162_rn(
                            pf[k].x - __bfloat162float(h2.x),
                            pf[k].y - __bfloat162float(h2.y));
                        u32 off = (u32)(row * 128) + (u32)((kp * 4) ^ ((row & 7) << 4));
                        *(u32*)(base + off)        = bf2u(h2);
                        *(u32*)(base + 8192 + off) = bf2u(l2);
                    }
                } else {
                    #pragma unroll
                    for (int k = 0; k < 4; k++) {
                        int f = tid + k * 512;
                        int row = f >> 5, kp = f & 31;
                        u32 off = (u32)(row * 128) + (u32)((kp * 4) ^ ((row & 7) << 4));
                        *(u32*)(base + off)        = ph[k];
                        *(u32*)(base + 8192 + off) = pl[k];
                    }
                }
            }
            __syncthreads();
        }

        // ---- epilogue: fast gate math; write h to regs, smem buf0 (own chunk),
        //      bf16 exchange arrays, and fp32 g_ys ----
        #pragma unroll
        for (int e = 0; e < 2; e++) {
            int rowl = wm * 16 + l4 + 8 * e;
            int rowg = b0 + rowl;
            float xv = e ? xv1 : xv0;
            #pragma unroll
            for (int sub = 0; sub < 2; sub++) {
                int jl = wn * 16 + 8 * sub + 2 * lp;
                float hn0, hn1;
                {
                    int j = jl;
                    float r = fast_sigmoid(xv * sparam[j] + sparam[192 + j]
                                           + A.a[0][sub][e * 2]);
                    float z = fast_sigmoid(xv * sparam[64 + j] + sparam[256 + j]
                                           + A.a[1][sub][e * 2]);
                    float n = fast_tanh(xv * sparam[128 + j] + sparam[320 + j]
                                        + r * (A.a[2][sub][e * 2] + sparam[384 + j]));
                    hn0 = (1.f - z) * n + z * hst[e][sub].x;
                }
                {
                    int j = jl + 1;
                    float r = fast_sigmoid(xv * sparam[j] + sparam[192 + j]
                                           + A.a[0][sub][e * 2 + 1]);
                    float z = fast_sigmoid(xv * sparam[64 + j] + sparam[256 + j]
                                           + A.a[1][sub][e * 2 + 1]);
                    float n = fast_tanh(xv * sparam[128 + j] + sparam[320 + j]
                                        + r * (A.a[2][sub][e * 2 + 1] + sparam[384 + j]));
                    hn1 = (1.f - z) * n + z * hst[e][sub].y;
                }
                hst[e][sub] = make_float2(hn0, hn1);
                *(float2*)&hout[(size_t)rowg * H + j0 + jl] = hst[e][sub];

                __nv_bfloat162 h2 = __floats2bfloat162_rn(hn0, hn1);
                __nv_bfloat162 l2 = __floats2bfloat162_rn(hn0 - __bfloat162float(h2.x),
                                                          hn1 - __bfloat162float(h2.y));
                int kp = wn * 8 + 4 * sub + lp;
                // global exchange for siblings
                size_t gi = (size_t)rowg * 128 + jc * 32 + kp;
                g_hhi[gi] = bf2u(h2);
                g_hlo[gi] = bf2u(l2);
                // own chunk straight into buf0 for next step
                u32 off = (u32)(rowl * 128) + (u32)((kp * 4) ^ ((rowl & 7) << 4));
                *(u32*)(smem + SM_A + off)        = bf2u(h2);
                *(u32*)(smem + SM_A + 8192 + off) = bf2u(l2);
            }
        }

        // ---- arrive (release h_t to siblings); also orders buf0 for next MMA ----
        if (t < T - 1) {
            __threadfence();
            __syncthreads();
            if (tid == 0) {
                u32 target = gen0 + (u32)t + 1u;
                u32 old = atomicAdd(&g_cnt[bg * 32], 1u);
                if (old == 3u) {
                    atomicExch(&g_cnt[bg * 32], 0u);
                    __threadfence();
                    atomicExch(&g_gen[bg * 32], target);
                }
            }
            __syncthreads();
        }
    }
}

// ---------------------------------------------------------------------------
// Fused MLP: fp32, fast elu, fp32x2 in stage 3.
// ---------------------------------------------------------------------------
constexpr int RROWS = 64;
constexpr int MLP_SMEM = (16384 + 16640 + 4096 + 4224) * 4;

__global__ void __launch_bounds__(256)
mlp_kernel(const float* __restrict__ w1, const float* __restrict__ b1,
           const float* __restrict__ w2, const float* __restrict__ b2,
           const float* __restrict__ w3, const float* __restrict__ b3,
           float* __restrict__ out)
{
    extern __shared__ float sm[];
    float* xt  = sm;
    float* w1s = sm + 16384;
    float* h1s = sm + 33024;
    float* h2t = sm + 37120;
    float* w3s = sm;
    float* w2s = sm + 16384;

    const int tid = threadIdx.x;
    const size_t row0 = (size_t)blockIdx.x * RROWS;

    {
        const float4* src = (const float4*)(g_ys + row0 * H);
        float4* dst = (float4*)xt;
        for (int i = tid; i < RROWS * H / 4; i += 256) dst[i] = src[i];
    }
    for (int f = tid; f < H * H1; f += 256) {
        int jj = f & 63; int k = f >> 6;
        w1s[jj * 260 + k] = w1[f];
    }
    __syncthreads();

    const int jp = tid & 31;
    const int rg = tid >> 5;

    // Stage 1
    {
        float acc[8][2];
        #pragma unroll
        for (int i = 0; i < 8; i++) { acc[i][0] = 0.f; acc[i][1] = 0.f; }
        #pragma unroll 4
        for (int k = 0; k < H; k += 4) {
            float4 wa = *(const float4*)&w1s[(2 * jp) * 260 + k];
            float4 wb = *(const float4*)&w1s[(2 * jp + 1) * 260 + k];
            #pragma unroll
            for (int i = 0; i < 8; i++) {
                float4 xv = *(const float4*)&xt[(rg * 8 + i) * H + k];
                acc[i][0] += xv.x * wa.x + xv.y * wa.y + xv.z * wa.z + xv.w * wa.w;
                acc[i][1] += xv.x * wb.x + xv.y * wb.y + xv.z * wb.z + xv.w * wb.w;
            }
        }
        float ba = b1[2 * jp], bb = b1[2 * jp + 1];
        #pragma unroll
        for (int i = 0; i < 8; i++) {
            h1s[(rg * 8 + i) * 64 + 2 * jp]     = fast_elu(acc[i][0] + ba);
            h1s[(rg * 8 + i) * 64 + 2 * jp + 1] = fast_elu(acc[i][1] + bb);
        }
    }
    __syncthreads();

    for (int f = tid; f < H1 * H2; f += 256) {
        int jj = f & 63; int k = f >> 6;
        w2s[jj * 68 + k] = w2[f];
    }
    __syncthreads();

    // Stage 2 (h2 transposed)
    {
        float acc[8][2];
        #pragma unroll
        for (int i = 0; i < 8; i++) { acc[i][0] = 0.f; acc[i][1] = 0.f; }
        #pragma unroll
        for (int k = 0; k < H1; k += 4) {
            float4 wa = *(const float4*)&w2s[(2 * jp) * 68 + k];
            float4 wb = *(const float4*)&w2s[(2 * jp + 1) * 68 + k];
            #pragma unroll
            for (int i = 0; i < 8; i++) {
                float4 xv = *(const float4*)&h1s[(rg * 8 + i) * 64 + k];
                acc[i][0] += xv.x * wa.x + xv.y * wa.y + xv.z * wa.z + xv.w * wa.w;
                acc[i][1] += xv.x * wb.x + xv.y * wb.y + xv.z * wb.z + xv.w * wb.w;
            }
        }
        float ba = b2[2 * jp], bb = b2[2 * jp + 1];
        #pragma unroll
        for (int i = 0; i < 8; i++) {
            int row = rg * 8 + i;
            h2t[(2 * jp) * 66 + row]     = fast_elu(acc[i][0] + ba);
            h2t[(2 * jp + 1) * 66 + row] = fast_elu(acc[i][1] + bb);
        }
    }
    __syncthreads();

    // Stage 3: packed fp32x2
    const int cp  = tid & 31;
    const int rg3 = tid >> 5;

    for (int c0 = 0; c0 < OUTD; c0 += 128) {
        for (int f = tid; f < 64 * 128; f += 256) {
            int c = f & 127; int k = f >> 7;
            int cg = c0 + c;
            w3s[k * 128 + c] = (cg < OUTD) ? w3[(size_t)k * OUTD + cg] : 0.f;
        }
        __syncthreads();

        u64 acc[4][4];
        #pragma unroll
        for (int rp = 0; rp < 4; rp++)
            #pragma unroll
            for (int q = 0; q < 4; q++) acc[rp][q] = 0ull;

        #pragma unroll 4
        for (int k = 0; k < H2; k++) {
            u64 wd[4];
            #pragma unroll
            for (int q = 0; q < 4; q++) {
                float w = w3s[k * 128 + cp + 32 * q];
                wd[q] = pack2(w, w);
            }
            const float* hp = &h2t[k * 66 + rg3 * 8];
            u64 hv0 = *(const u64*)(hp + 0);
            u64 hv1 = *(const u64*)(hp + 2);
            u64 hv2 = *(const u64*)(hp + 4);
            u64 hv3 = *(const u64*)(hp + 6);
            #pragma unroll
            for (int q = 0; q < 4; q++) {
                acc[0][q] = ffma2(hv0, wd[q], acc[0][q]);
                acc[1][q] = ffma2(hv1, wd[q], acc[1][q]);
                acc[2][q] = ffma2(hv2, wd[q], acc[2][q]);
                acc[3][q] = ffma2(hv3, wd[q], acc[3][q]);
            }
        }

        #pragma unroll
        for (int q = 0; q < 4; q++) {
            int cg = c0 + cp + 32 * q;
            if (cg < OUTD) {
                float bq = b3[cg];
                #pragma unroll
                for (int rp = 0; rp < 4; rp++) {
                    float2 v = unpack2(acc[rp][q]);
                    size_t row = row0 + rg3 * 8 + 2 * rp;
                    out[row * OUTD + cg]       = v.x + bq;
                    out[(row + 1) * OUTD + cg] = v.y + bq;
                }
            }
        }
        __syncthreads();
    }
}

__global__ void copy_h_kernel(float* __restrict__ out)
{
    int i = blockIdx.x * blockDim.x + threadIdx.x;
    if (i < B * H / 4) {
        const float4* src = (const float4*)(g_ys + (size_t)(T - 1) * B * H);
        ((float4*)out)[i] = src[i];
    }
}

// ---------------------------------------------------------------------------
extern "C" void kernel_launch(void* const* d_in, const int* in_sizes, int n_in,
                              void* d_out, int out_size)
{
    const float* x    = (const float*)d_in[0];
    const float* h0   = (const float*)d_in[1];
    const float* w_ih = (const float*)d_in[2];
    const float* w_hh = (const float*)d_in[3];
    const float* b_ih = (const float*)d_in[4];
    const float* b_hh = (const float*)d_in[5];
    const float* w1   = (const float*)d_in[6];
    const float* b1   = (const float*)d_in[7];
    const float* w2   = (const float*)d_in[8];
    const float* b2   = (const float*)d_in[9];
    const float* w3   = (const float*)d_in[10];
    const float* b3   = (const float*)d_in[11];
    float* out = (float*)d_out;

    cudaFuncSetAttribute(gru_persist,
                         cudaFuncAttributeMaxDynamicSharedMemorySize, GRU_SMEM);
    cudaFuncSetAttribute(mlp_kernel,
                         cudaFuncAttributeMaxDynamicSharedMemorySize, MLP_SMEM);

    prep_w_kernel<<<(3 * H * H + 255) / 256, 256>>>(w_hh);

    gru_persist<<<NBLK, 512, GRU_SMEM>>>(h0, x, w_ih, b_ih, b_hh);

    mlp_kernel<<<(T * B) / RROWS, 256, MLP_SMEM>>>(w1, b1, w2, b2, w3, b3, out);

    copy_h_kernel<<<(B * H / 4 + 255) / 256, 256>>>(out + (size_t)T * B * OUTD);
}

// round 8
// speedup vs baseline: 3.0041x; 1.3120x over previous
#include <cuda_runtime.h>
#include <cuda_bf16.h>
#include <math.h>
#include <string.h>

typedef unsigned int u32;
typedef unsigned long long u64;

// ---------------------------------------------------------------------------
// Problem constants
// ---------------------------------------------------------------------------
constexpr int T    = 64;
constexpr int B    = 2048;
constexpr int H    = 256;
constexpr int H1   = 64;
constexpr int H2   = 64;
constexpr int OUTD = 601;
constexpr int RROWS = 64;
constexpr int NTILE = T * B / RROWS;   // 2048 MLP tiles

// ---------------------------------------------------------------------------
// PTX helpers
// ---------------------------------------------------------------------------
__device__ __forceinline__ u32 smem_u32(const void* p) {
    u32 a;
    asm("{ .reg .u64 t; cvta.to.shared.u64 t, %1; cvt.u32.u64 %0, t; }"
        : "=r"(a) : "l"(p));
    return a;
}
__device__ __forceinline__ void ldsm_x4(u32& r0, u32& r1, u32& r2, u32& r3, u32 addr) {
    asm volatile("ldmatrix.sync.aligned.m8n8.x4.shared.b16 {%0,%1,%2,%3}, [%4];"
                 : "=r"(r0), "=r"(r1), "=r"(r2), "=r"(r3) : "r"(addr));
}
__device__ __forceinline__ void mma_bf16(float* d, const u32* a, const u32* b) {
    asm volatile(
        "mma.sync.aligned.m16n8k16.row.col.f32.bf16.bf16.f32 "
        "{%0,%1,%2,%3}, {%4,%5,%6,%7}, {%8,%9}, {%0,%1,%2,%3};"
        : "+f"(d[0]), "+f"(d[1]), "+f"(d[2]), "+f"(d[3])
        : "r"(a[0]), "r"(a[1]), "r"(a[2]), "r"(a[3]), "r"(b[0]), "r"(b[1]));
}
__device__ __forceinline__ void cp16(u32 dst, const void* src) {
    asm volatile("cp.async.ca.shared.global [%0], [%1], 16;" :: "r"(dst), "l"(src));
}
__device__ __forceinline__ void cp_commit() {
    asm volatile("cp.async.commit_group;" ::: "memory");
}
template <int N>
__device__ __forceinline__ void cp_wait_group() {
    asm volatile("cp.async.wait_group %0;" :: "n"(N) : "memory");
}
__device__ __forceinline__ void cp_wait_all() {
    asm volatile("cp.async.wait_all;" ::: "memory");
}
__device__ __forceinline__ u32 bf2u(__nv_bfloat162 v) {
    u32 r; memcpy(&r, &v, 4); return r;
}
__device__ __forceinline__ u64 ffma2(u64 a, u64 b, u64 c) {
    u64 d; asm("fma.rn.f32x2 %0, %1, %2, %3;" : "=l"(d) : "l"(a), "l"(b), "l"(c));
    return d;
}
__device__ __forceinline__ u64 pack2(float x, float y) {
    u64 d; asm("mov.b64 %0, {%1, %2};" : "=l"(d) : "f"(x), "f"(y));
    return d;
}
__device__ __forceinline__ float2 unpack2(u64 v) {
    float2 r; asm("mov.b64 {%0, %1}, %2;" : "=f"(r.x), "=f"(r.y) : "l"(v));
    return r;
}
constexpr float LOG2E = 1.4426950408889634f;
__device__ __forceinline__ float fast_sigmoid(float v) {
    float e; asm("ex2.approx.f32 %0, %1;" : "=f"(e) : "f"(-LOG2E * v));
    float r; asm("rcp.approx.f32 %0, %1;" : "=f"(r) : "f"(1.f + e));
    return r;
}
__device__ __forceinline__ float fast_tanh(float v) {
    float e; asm("ex2.approx.f32 %0, %1;" : "=f"(e) : "f"(2.f * LOG2E * v));
    float r; asm("rcp.approx.f32 %0, %1;" : "=f"(r) : "f"(1.f + e));
    return 1.f - 2.f * r;
}
__device__ __forceinline__ float fast_elu(float v) {
    if (v > 0.f) return v;
    float e; asm("ex2.approx.f32 %0, %1;" : "=f"(e) : "f"(LOG2E * v));
    return e - 1.f;
}

// ---------------------------------------------------------------------------
// Device scratch
// ---------------------------------------------------------------------------
__device__ float g_ys[(size_t)T * B * H];
__device__ __nv_bfloat16 g_whi[(size_t)3 * H * H];
__device__ __nv_bfloat16 g_wlo[(size_t)3 * H * H];
__device__ u32 g_hhi[(size_t)B * H / 2];
__device__ u32 g_hlo[(size_t)B * H / 2];
__device__ u32 g_cnt[32 * 32];    // per-bg arrival counters (128B apart)
__device__ u32 g_gen[32 * 32];    // per-bg completed-step counters (absolute)
__device__ u32 g_q;               // MLP tile queue

__global__ void prep_w_kernel(const float* __restrict__ w_hh)
{
    int i = blockIdx.x * blockDim.x + threadIdx.x;
    if (i < 3 * H * H) {
        float w = w_hh[i];
        __nv_bfloat16 hi = __float2bfloat16(w);
        g_whi[i] = hi;
        g_wlo[i] = __float2bfloat16(w - __bfloat162float(hi));
    }
    if (blockIdx.x == 0 && threadIdx.x < 32) {
        g_cnt[threadIdx.x * 32] = 0;
        g_gen[threadIdx.x * 32] = 0;
        if (threadIdx.x == 0) g_q = 0;
    }
}

// ---------------------------------------------------------------------------
// Fused persistent kernel: 148 blocks x 512 threads.
// Blocks 0..127: GRU producer (4 j-chunks x 32 batch-groups), then join MLP.
// Blocks 128..147: MLP consumers from the start (tile queue, gated on g_gen).
// ---------------------------------------------------------------------------
constexpr int GRID_P = 148;
constexpr int NGRU   = 128;
constexpr int SM_W      = 0;        // whi [4][192][128B]=98304 ; wlo at +98304
constexpr int SM_WLO_O  = 98304;
constexpr int SM_A      = 196608;   // 2 bufs x (hi 8192 + lo 8192)
constexpr int SM_PRM    = 229376;   // 7*64 f32 = 1792B
constexpr int SM_Q      = 231168;   // queue broadcast slot
constexpr int FUSED_SMEM = 231296;

struct AccT { float a[3][2][4]; };

__device__ __forceinline__ void mma_section(AccT& A, u32 ab, u32 wb,
                                            int wm, int wn,
                                            int a_row, int a_colh,
                                            int b_row, int b_colh)
{
    #pragma unroll
    for (int ks = 0; ks < 4; ks++) {
        u32 ahi[4], alo[4];
        {
            int r = wm * 16 + a_row;
            u32 off = (u32)(r * 128) + (u32)((ks * 32 + a_colh) ^ ((r & 7) << 4));
            ldsm_x4(ahi[0], ahi[1], ahi[2], ahi[3], ab + off);
            ldsm_x4(alo[0], alo[1], alo[2], alo[3], ab + 8192 + off);
        }
        #pragma unroll
        for (int g = 0; g < 3; g++) {
            int rr = g * 64 + wn * 16 + b_row;
            u32 off = (u32)(rr * 128) + (u32)((ks * 32 + b_colh) ^ ((rr & 7) << 4));
            u32 bh[4], bl[4];
            ldsm_x4(bh[0], bh[1], bh[2], bh[3], wb + off);
            ldsm_x4(bl[0], bl[1], bl[2], bl[3], wb + SM_WLO_O + off);
            mma_bf16(A.a[g][0], ahi, bh);
            mma_bf16(A.a[g][1], ahi, bh + 2);
            mma_bf16(A.a[g][0], ahi, bl);
            mma_bf16(A.a[g][1], ahi, bl + 2);
            mma_bf16(A.a[g][0], alo, bh);
            mma_bf16(A.a[g][1], alo, bh + 2);
        }
    }
}

__global__ void __launch_bounds__(512, 1)
fused_persist(const float* __restrict__ h0,
              const float* __restrict__ x,
              const float* __restrict__ w_ih,
              const float* __restrict__ b_ih,
              const float* __restrict__ b_hh,
              const float* __restrict__ w1, const float* __restrict__ b1,
              const float* __restrict__ w2, const float* __restrict__ b2,
              const float* __restrict__ w3, const float* __restrict__ b3,
              float* __restrict__ out)
{
    extern __shared__ char smem[];
    const u32 sb = smem_u32(smem);
    const int tid  = threadIdx.x;

    // =====================================================================
    // GRU producer part (blocks 0..NGRU-1)
    // =====================================================================
    if (blockIdx.x < NGRU) {
        float* sparam = (float*)(smem + SM_PRM);
        const int wid  = tid >> 5;
        const int lane = tid & 31;
        const int jc = blockIdx.x & 3;
        const int bg = blockIdx.x >> 2;
        const int j0 = jc * 64;
        const int b0 = bg * 64;
        const int wm = wid >> 2;
        const int wn = wid & 3;

        if (tid < 64) {
            int jg = j0 + tid;
            sparam[tid]        = w_ih[jg];
            sparam[64 + tid]   = w_ih[H + jg];
            sparam[128 + tid]  = w_ih[2 * H + jg];
            sparam[192 + tid]  = b_ih[jg]         + b_hh[jg];
            sparam[256 + tid]  = b_ih[H + jg]     + b_hh[H + jg];
            sparam[320 + tid]  = b_ih[2 * H + jg];
            sparam[384 + tid]  = b_hh[2 * H + jg];
        }

        // stage all weights once (bf16 hi/lo, SW128)
        for (int c = 0; c < 4; c++) {
            for (int f = tid; f < 192 * 8; f += 512) {
                int rr = f >> 3, cc = f & 7;
                int g = rr >> 6, jj = rr & 63;
                size_t src = ((size_t)(g * H + j0 + jj)) * H + c * 64 + cc * 8;
                u32 d = sb + SM_W + c * 24576 + rr * 128 + ((cc * 16) ^ ((rr & 7) << 4));
                cp16(d, g_whi + src);
                cp16(d + SM_WLO_O, g_wlo + src);
            }
        }

        const int a_row  = lane & 15;
        const int a_colh = (lane >> 4) * 16;
        const int b_row  = ((lane >> 4) << 3) + (lane & 7);
        const int b_colh = ((lane >> 3) & 1) * 16;
        const int l4 = lane >> 2;
        const int lp = lane & 3;

        float2 hst[2][2];
        #pragma unroll
        for (int e = 0; e < 2; e++)
            #pragma unroll
            for (int sub = 0; sub < 2; sub++) {
                int rowg = b0 + wm * 16 + l4 + 8 * e;
                int jl = wn * 16 + 8 * sub + 2 * lp;
                hst[e][sub] = *(const float2*)&h0[(size_t)rowg * H + j0 + jl];
            }

        // pre-stage own chunk of h0 into buf0
        #pragma unroll
        for (int i = 0; i < 4; i++) {
            int f = tid + i * 512;
            int row = f >> 5, kp = f & 31;
            float2 hv = *(const float2*)&h0[(size_t)(b0 + row) * H + jc * 64 + 2 * kp];
            __nv_bfloat162 h2 = __floats2bfloat162_rn(hv.x, hv.y);
            __nv_bfloat162 l2 = __floats2bfloat162_rn(hv.x - __bfloat162float(h2.x),
                                                      hv.y - __bfloat162float(h2.y));
            u32 off = (u32)(row * 128) + (u32)((kp * 4) ^ ((row & 7) << 4));
            *(u32*)(smem + SM_A + off)        = bf2u(h2);
            *(u32*)(smem + SM_A + 8192 + off) = bf2u(l2);
        }
        cp_wait_all();
        __syncthreads();

        const u32 ab0 = sb + SM_A;
        const u32 ab1 = sb + SM_A + 16384;
        const int crow = tid >> 3;       // cp-stage row (64 rows x 8 groups)
        const int cgrp = tid & 7;
        const u32 coff = (u32)(crow * 128) + (u32)((cgrp * 16) ^ ((crow & 7) << 4));

        for (int t = 0; t < T; t++) {
            float xv0 = x[(size_t)t * B + b0 + wm * 16 + l4];
            float xv1 = x[(size_t)t * B + b0 + wm * 16 + l4 + 8];

            AccT A;
            #pragma unroll
            for (int g = 0; g < 3; g++)
                #pragma unroll
                for (int s = 0; s < 2; s++)
                    #pragma unroll
                    for (int q = 0; q < 4; q++) A.a[g][s][q] = 0.f;

            // own chunk first (no barrier needed)
            mma_section(A, ab0, sb + SM_W + jc * 24576, wm, wn, a_row, a_colh, b_row, b_colh);

            if (t > 0 && tid == 0) {
                u32 g;
                do {
                    asm volatile("ld.acquire.gpu.global.u32 %0, [%1];"
                                 : "=r"(g) : "l"(&g_gen[bg * 32]));
                } while ((int)(g - (u32)t) < 0);
            }
            __syncthreads();   // gen visible to block + all warps past own-chunk MMA

            if (t == 0) {
                // serial register staging from h0 (once)
                #pragma unroll
                for (int i = 1; i <= 3; i++) {
                    int c = (jc + i) & 3;
                    char* base = smem + SM_A + ((i & 1) ? 16384 : 0);
                    #pragma unroll
                    for (int k = 0; k < 4; k++) {
                        int f = tid + k * 512;
                        int row = f >> 5, kp = f & 31;
                        float2 hv = *(const float2*)&h0[(size_t)(b0 + row) * H + c * 64 + 2 * kp];
                        __nv_bfloat162 h2 = __floats2bfloat162_rn(hv.x, hv.y);
                        __nv_bfloat162 l2 = __floats2bfloat162_rn(hv.x - __bfloat162float(h2.x),
                                                                  hv.y - __bfloat162float(h2.y));
                        u32 off = (u32)(row * 128) + (u32)((kp * 4) ^ ((row & 7) << 4));
                        *(u32*)(base + off)        = bf2u(h2);
                        *(u32*)(base + 8192 + off) = bf2u(l2);
                    }
                    __syncthreads();
                    mma_section(A, (i & 1) ? ab1 : ab0, sb + SM_W + c * 24576,
                                wm, wn, a_row, a_colh, b_row, b_colh);
                    if (i < 3) __syncthreads();
                }
            } else {
                // cp.async pipelined staging of sibling chunks
                int c1 = (jc + 1) & 3, c2 = (jc + 2) & 3, c3 = (jc + 3) & 3;
                const u32* s1h = &g_hhi[(size_t)(b0 + crow) * 128 + c1 * 32 + cgrp * 4];
                const u32* s1l = &g_hlo[(size_t)(b0 + crow) * 128 + c1 * 32 + cgrp * 4];
                cp16(ab1 + coff, s1h);
                cp16(ab1 + 8192 + coff, s1l);
                cp_commit();                                          // group A
                const u32* s2h = &g_hhi[(size_t)(b0 + crow) * 128 + c2 * 32 + cgrp * 4];
                const u32* s2l = &g_hlo[(size_t)(b0 + crow) * 128 + c2 * 32 + cgrp * 4];
                cp16(ab0 + coff, s2h);
                cp16(ab0 + 8192 + coff, s2l);
                cp_commit();                                          // group B
                cp_wait_group<1>();
                __syncthreads();
                mma_section(A, ab1, sb + SM_W + c1 * 24576, wm, wn, a_row, a_colh, b_row, b_colh);
                cp_wait_group<0>();
                __syncthreads();
                const u32* s3h = &g_hhi[(size_t)(b0 + crow) * 128 + c3 * 32 + cgrp * 4];
                const u32* s3l = &g_hlo[(size_t)(b0 + crow) * 128 + c3 * 32 + cgrp * 4];
                cp16(ab1 + coff, s3h);
                cp16(ab1 + 8192 + coff, s3l);
                cp_commit();                                          // group C
                mma_section(A, ab0, sb + SM_W + c2 * 24576, wm, wn, a_row, a_colh, b_row, b_colh);
                cp_wait_group<0>();
                __syncthreads();
                mma_section(A, ab1, sb + SM_W + c3 * 24576, wm, wn, a_row, a_colh, b_row, b_colh);
            }

            // epilogue: gates; update regs; write g_ys, bf16 exchange, buf0
            float* hout = g_ys + (size_t)t * B * H;
            #pragma unroll
            for (int e = 0; e < 2; e++) {
                int rowl = wm * 16 + l4 + 8 * e;
                int rowg = b0 + rowl;
                float xv = e ? xv1 : xv0;
                #pragma unroll
                for (int sub = 0; sub < 2; sub++) {
                    int jl = wn * 16 + 8 * sub + 2 * lp;
                    float hn0, hn1;
                    {
                        int j = jl;
                        float r = fast_sigmoid(xv * sparam[j] + sparam[192 + j]
                                               + A.a[0][sub][e * 2]);
                        float z = fast_sigmoid(xv * sparam[64 + j] + sparam[256 + j]
                                               + A.a[1][sub][e * 2]);
                        float n = fast_tanh(xv * sparam[128 + j] + sparam[320 + j]
                                            + r * (A.a[2][sub][e * 2] + sparam[384 + j]));
                        hn0 = (1.f - z) * n + z * hst[e][sub].x;
                    }
                    {
                        int j = jl + 1;
                        float r = fast_sigmoid(xv * sparam[j] + sparam[192 + j]
                                               + A.a[0][sub][e * 2 + 1]);
                        float z = fast_sigmoid(xv * sparam[64 + j] + sparam[256 + j]
                                               + A.a[1][sub][e * 2 + 1]);
                        float n = fast_tanh(xv * sparam[128 + j] + sparam[320 + j]
                                            + r * (A.a[2][sub][e * 2 + 1] + sparam[384 + j]));
                        hn1 = (1.f - z) * n + z * hst[e][sub].y;
                    }
                    hst[e][sub] = make_float2(hn0, hn1);
                    *(float2*)&hout[(size_t)rowg * H + j0 + jl] = hst[e][sub];

                    __nv_bfloat162 h2 = __floats2bfloat162_rn(hn0, hn1);
                    __nv_bfloat162 l2 = __floats2bfloat162_rn(hn0 - __bfloat162float(h2.x),
                                                              hn1 - __bfloat162float(h2.y));
                    int kp = wn * 8 + 4 * sub + lp;
                    size_t gi = (size_t)rowg * 128 + jc * 32 + kp;
                    g_hhi[gi] = bf2u(h2);
                    g_hlo[gi] = bf2u(l2);
                    u32 off = (u32)(rowl * 128) + (u32)((kp * 4) ^ ((rowl & 7) << 4));
                    *(u32*)(smem + SM_A + off)        = bf2u(h2);
                    *(u32*)(smem + SM_A + 8192 + off) = bf2u(l2);
                }
            }

            // release h_t (every step; consumers need t=T-1 too)
            __threadfence();
            __syncthreads();
            if (tid == 0) {
                u32 old = atomicAdd(&g_cnt[bg * 32], 1u);
                if (old == 3u) {
                    atomicExch(&g_cnt[bg * 32], 0u);
                    __threadfence();
                    atomicExch(&g_gen[bg * 32], (u32)t + 1u);
                }
            }
        }
        __syncthreads();
    }

    // =====================================================================
    // MLP consumer part (all blocks; queue-driven, gated on g_gen)
    // =====================================================================
    {
        float* sm  = (float*)smem;
        float* xt  = sm;            // [64][256]
        float* w1s = sm + 16384;    // [64][260]
        float* h1s = sm + 33024;    // [64][64]
        float* h2t = sm + 37120;    // [64][66]
        float* w3s = sm;            // alias xt
        float* w2s = sm + 16384;    // alias w1s
        u32* qs = (u32*)(smem + SM_Q);

        const int jp = tid & 31;
        const int rg = (tid >> 5) & 7;
        const bool act = tid < 256;

        for (;;) {
            __syncthreads();
            if (tid == 0) *qs = atomicAdd(&g_q, 1u);
            __syncthreads();
            u32 q = *qs;
            if (q >= (u32)NTILE) break;
            int tt  = (int)(q >> 5);
            int bgq = (int)(q & 31);

            if (tid == 0) {
                u32 target = (u32)tt + 1u, g;
                do {
                    asm volatile("ld.acquire.gpu.global.u32 %0, [%1];"
                                 : "=r"(g) : "l"(&g_gen[bgq * 32]));
                } while ((int)(g - target) < 0);
            }
            __syncthreads();

            const size_t row0 = (size_t)q * RROWS;

            {
                const float4* src = (const float4*)(g_ys + row0 * H);
                float4* dst = (float4*)xt;
                for (int i = tid; i < RROWS * H / 4; i += 512) dst[i] = src[i];
            }
            for (int f = tid; f < H * H1; f += 512) {
                int jj = f & 63; int k = f >> 6;
                w1s[jj * 260 + k] = w1[f];
            }
            __syncthreads();

            // Stage 1
            if (act) {
                float acc[8][2];
                #pragma unroll
                for (int i = 0; i < 8; i++) { acc[i][0] = 0.f; acc[i][1] = 0.f; }
                #pragma unroll 4
                for (int k = 0; k < H; k += 4) {
                    float4 wa = *(const float4*)&w1s[(2 * jp) * 260 + k];
                    float4 wb = *(const float4*)&w1s[(2 * jp + 1) * 260 + k];
                    #pragma unroll
                    for (int i = 0; i < 8; i++) {
                        float4 xv = *(const float4*)&xt[(rg * 8 + i) * H + k];
                        acc[i][0] += xv.x * wa.x + xv.y * wa.y + xv.z * wa.z + xv.w * wa.w;
                        acc[i][1] += xv.x * wb.x + xv.y * wb.y + xv.z * wb.z + xv.w * wb.w;
                    }
                }
                float ba = b1[2 * jp], bb = b1[2 * jp + 1];
                #pragma unroll
                for (int i = 0; i < 8; i++) {
                    h1s[(rg * 8 + i) * 64 + 2 * jp]     = fast_elu(acc[i][0] + ba);
                    h1s[(rg * 8 + i) * 64 + 2 * jp + 1] = fast_elu(acc[i][1] + bb);
                }
            }
            __syncthreads();

            for (int f = tid; f < H1 * H2; f += 512) {
                int jj = f & 63; int k = f >> 6;
                w2s[jj * 68 + k] = w2[f];
            }
            __syncthreads();

            // Stage 2 (h2 transposed)
            if (act) {
                float acc[8][2];
                #pragma unroll
                for (int i = 0; i < 8; i++) { acc[i][0] = 0.f; acc[i][1] = 0.f; }
                #pragma unroll
                for (int k = 0; k < H1; k += 4) {
                    float4 wa = *(const float4*)&w2s[(2 * jp) * 68 + k];
                    float4 wb = *(const float4*)&w2s[(2 * jp + 1) * 68 + k];
                    #pragma unroll
                    for (int i = 0; i < 8; i++) {
                        float4 xv = *(const float4*)&h1s[(rg * 8 + i) * 64 + k];
                        acc[i][0] += xv.x * wa.x + xv.y * wa.y + xv.z * wa.z + xv.w * wa.w;
                        acc[i][1] += xv.x * wb.x + xv.y * wb.y + xv.z * wb.z + xv.w * wb.w;
                    }
                }
                float ba = b2[2 * jp], bb = b2[2 * jp + 1];
                #pragma unroll
                for (int i = 0; i < 8; i++) {
                    int row = rg * 8 + i;
                    h2t[(2 * jp) * 66 + row]     = fast_elu(acc[i][0] + ba);
                    h2t[(2 * jp + 1) * 66 + row] = fast_elu(acc[i][1] + bb);
                }
            }
            __syncthreads();

            // Stage 3: packed fp32x2 over row pairs
            for (int c0 = 0; c0 < OUTD; c0 += 128) {
                for (int f = tid; f < 64 * 128; f += 512) {
                    int c = f & 127; int k = f >> 7;
                    int cg = c0 + c;
                    w3s[k * 128 + c] = (cg < OUTD) ? w3[(size_t)k * OUTD + cg] : 0.f;
                }
                __syncthreads();

                if (act) {
                    const int cp  = jp;
                    const int rg3 = rg;
                    u64 acc[4][4];
                    #pragma unroll
                    for (int rp = 0; rp < 4; rp++)
                        #pragma unroll
                        for (int qq = 0; qq < 4; qq++) acc[rp][qq] = 0ull;

                    #pragma unroll 4
                    for (int k = 0; k < H2; k++) {
                        u64 wd[4];
                        #pragma unroll
                        for (int qq = 0; qq < 4; qq++) {
                            float w = w3s[k * 128 + cp + 32 * qq];
                            wd[qq] = pack2(w, w);
                        }
                        const float* hp = &h2t[k * 66 + rg3 * 8];
                        u64 hv0 = *(const u64*)(hp + 0);
                        u64 hv1 = *(const u64*)(hp + 2);
                        u64 hv2 = *(const u64*)(hp + 4);
                        u64 hv3 = *(const u64*)(hp + 6);
                        #pragma unroll
                        for (int qq = 0; qq < 4; qq++) {
                            acc[0][qq] = ffma2(hv0, wd[qq], acc[0][qq]);
                            acc[1][qq] = ffma2(hv1, wd[qq], acc[1][qq]);
                            acc[2][qq] = ffma2(hv2, wd[qq], acc[2][qq]);
                            acc[3][qq] = ffma2(hv3, wd[qq], acc[3][qq]);
                        }
                    }

                    #pragma unroll
                    for (int qq = 0; qq < 4; qq++) {
                        int cg = c0 + cp + 32 * qq;
                        if (cg < OUTD) {
                            float bq = b3[cg];
                            #pragma unroll
                            for (int rp = 0; rp < 4; rp++) {
                                float2 v = unpack2(acc[rp][qq]);
                                size_t row = row0 + rg3 * 8 + 2 * rp;
                                out[row * OUTD + cg]       = v.x + bq;
                                out[(row + 1) * OUTD + cg] = v.y + bq;
                            }
                        }
                    }
                }
                __syncthreads();
            }
        }
    }
}

__global__ void copy_h_kernel(float* __restrict__ out)
{
    int i = blockIdx.x * blockDim.x + threadIdx.x;
    if (i < B * H / 4) {
        const float4* src = (const float4*)(g_ys + (size_t)(T - 1) * B * H);
        ((float4*)out)[i] = src[i];
    }
}

// ---------------------------------------------------------------------------
extern "C" void kernel_launch(void* const* d_in, const int* in_sizes, int n_in,
                              void* d_out, int out_size)
{
    const float* x    = (const float*)d_in[0];
    const float* h0   = (const float*)d_in[1];
    const float* w_ih = (const float*)d_in[2];
    const float* w_hh = (const float*)d_in[3];
    const float* b_ih = (const float*)d_in[4];
    const float* b_hh = (const float*)d_in[5];
    const float* w1   = (const float*)d_in[6];
    const float* b1   = (const float*)d_in[7];
    const float* w2   = (const float*)d_in[8];
    const float* b2   = (const float*)d_in[9];
    const float* w3   = (const float*)d_in[10];
    const float* b3   = (const float*)d_in[11];
    float* out = (float*)d_out;

    cudaFuncSetAttribute(fused_persist,
                         cudaFuncAttributeMaxDynamicSharedMemorySize, FUSED_SMEM);

    prep_w_kernel<<<(3 * H * H + 255) / 256, 256>>>(w_hh);

    fused_persist<<<GRID_P, 512, FUSED_SMEM>>>(h0, x, w_ih, b_ih, b_hh,
                                               w1, b1, w2, b2, w3, b3, out);

    copy_h_kernel<<<(B * H / 4 + 255) / 256, 256>>>(out + (size_t)T * B * OUTD);
}